// round 5
// baseline (speedup 1.0000x reference)
#include <cuda_runtime.h>

#define PNUM 16320
#define BATCH 32
#define NCLS 21
#define TOPK 500
#define CONF_THV 0.01f
#define NMS_THV 0.45f
#define OBJ_THV 0.01f
#define LISTCAP 4096

// ---- device scratch (no allocations allowed) ----
__device__ float4 g_boxes[BATCH * PNUM];                 // decoded boxes (x1,y1,x2,y2)
__device__ float  g_scores[BATCH * (NCLS - 1) * PNUM];   // arm-masked scores, [B][20][P]

// ---- shared memory layout (bytes) ----
#define OFF_MISC   0        // 128 (32 u32: flags + 16 alive words)
#define OFF_SELS   128      // 512*4
#define OFF_SELI   2176     // 512*4
#define OFF_BOX    4224     // 512*16 (16B aligned)
#define OFF_AREA   12416    // 512*4
#define OFF_PORD   14464    // 512*4
#define OFF_MAT    16512    // 512*16*4 = 32768
#define SMEM_TOTAL 49280    // 4 blocks/SM (64 warps = max)
// overlays inside MAT (dead before matrix phase starts)
#define OFF_KEYL   16512    // 4096*4
#define OFF_HIST   32896    // 2048*4
#define OFF_PART   41088    // 512*4 part + 32*4 wsum
#define OFF_EQ     43264    // 512*4

// misc map: 0=nlist 1=ncomp 2=THR 3=need_tie 4=rem/take 5=done 6=K 7=cnt
//           8=prefix 9=neq 11=binCount 13=tieTake 16..31=alive

// =====================================================================
// Kernel 1: cascaded decode + arm-masked score transpose
// =====================================================================
__global__ void prep_kernel(const float* __restrict__ arm_loc,
                            const float* __restrict__ arm_conf,
                            const float* __restrict__ odm_loc,
                            const float* __restrict__ odm_conf,
                            const float* __restrict__ priors) {
    int idx = blockIdx.x * blockDim.x + threadIdx.x;
    if (idx >= BATCH * PNUM) return;
    int b = idx / PNUM;
    int p = idx % PNUM;

    float pcx = priors[p * 4 + 0];
    float pcy = priors[p * 4 + 1];
    float pw  = priors[p * 4 + 2];
    float ph  = priors[p * 4 + 3];

    const float* al = arm_loc + (size_t)idx * 4;
    const float* ol = odm_loc + (size_t)idx * 4;

    float cx = pcx + al[0] * 0.1f * pw;
    float cy = pcy + al[1] * 0.1f * ph;
    float w  = pw * expf(al[2] * 0.2f);
    float h  = ph * expf(al[3] * 0.2f);
    float mnx = cx - w * 0.5f;
    float mny = cy - h * 0.5f;
    float mxx = mnx + w;
    float mxy = mny + h;
    float dcx = (mxx + mnx) * 0.5f;
    float dcy = (mxy + mny) * 0.5f;
    float dw  = mxx - mnx;
    float dh  = mxy - mny;

    float cx2 = dcx + ol[0] * 0.1f * dw;
    float cy2 = dcy + ol[1] * 0.1f * dh;
    float w2  = dw * expf(ol[2] * 0.2f);
    float h2  = dh * expf(ol[3] * 0.2f);
    float x1 = cx2 - w2 * 0.5f;
    float y1 = cy2 - h2 * 0.5f;
    float x2 = x1 + w2;
    float y2 = y1 + h2;
    g_boxes[idx] = make_float4(x1, y1, x2, y2);

    bool armpass = arm_conf[(size_t)idx * 2 + 1] > OBJ_THV;
    const float* oc = odm_conf + (size_t)idx * NCLS;
#pragma unroll
    for (int c = 1; c < NCLS; ++c) {
        float v = armpass ? oc[c] : 0.0f;
        g_scores[((size_t)(b * (NCLS - 1) + (c - 1))) * PNUM + p] = v;
    }
}

// =====================================================================
// Kernel 2: per (image,class): 32-bit radix select w/ list narrowing,
// bitonic sort, upper-triangle suppression bitmatrix, monotonic NMS walk.
// All warp-collective ops run on warp-uniform trip counts (padded loops).
// =====================================================================
__global__ void __launch_bounds__(512) task_kernel(float* __restrict__ out) {
    extern __shared__ __align__(16) char smraw[];
    unsigned* misc   = (unsigned*)(smraw + OFF_MISC);
    float*    sel_s  = (float*)(smraw + OFF_SELS);
    int*      sel_i  = (int*)(smraw + OFF_SELI);
    float4*   bx4    = (float4*)(smraw + OFF_BOX);
    float*    s_area = (float*)(smraw + OFF_AREA);
    int*      pord   = (int*)(smraw + OFF_PORD);
    unsigned* mat    = (unsigned*)(smraw + OFF_MAT);
    unsigned* keyl   = (unsigned*)(smraw + OFF_KEYL);
    unsigned* hist   = (unsigned*)(smraw + OFF_HIST);
    unsigned* part   = (unsigned*)(smraw + OFF_PART);
    unsigned* wsum   = (unsigned*)(smraw + OFF_PART + 2048);
    unsigned* eq     = (unsigned*)(smraw + OFF_EQ);

    const int tid = threadIdx.x;
    const int b   = blockIdx.x / NCLS;
    const int cl  = blockIdx.x % NCLS;
    float* outp = out + (size_t)(b * NCLS + cl) * (TOPK * 5);

    if (cl == 0) {
        for (int e = tid; e < TOPK * 5; e += 512) outp[e] = 0.0f;
        return;
    }

    const float* __restrict__ sp =
        g_scores + (size_t)(b * (NCLS - 1) + (cl - 1)) * PNUM;

    // ======== PASS A: full-scan histogram on key>>21 (2048 bins) ========
    for (int h = tid; h < 2048; h += 512) hist[h] = 0u;
    if (tid < 16) misc[tid] = 0u;
    __syncthreads();

    for (int j = tid; j < PNUM; j += 512) {  // 16320 % 512 = 448 (warp-aligned)
        float s = __ldg(&sp[j]);
        int bin = (s > CONF_THV) ? (int)(__float_as_uint(s) >> 21) : -1;
        unsigned grp = __match_any_sync(0xFFFFFFFFu, bin);
        if (((unsigned)tid & 31u) == (unsigned)(__ffs(grp) - 1) && bin >= 0)
            atomicAdd(&hist[bin], (unsigned)__popc(grp));
    }
    __syncthreads();

    // parallel reduce + thread-0 search (includes total/K)
    {
        unsigned s = hist[tid * 4] + hist[tid * 4 + 1] + hist[tid * 4 + 2] + hist[tid * 4 + 3];
        part[tid] = s;
        __syncthreads();
        if (tid < 32) {
            unsigned ws = 0;
            for (int q = 0; q < 16; ++q) ws += part[tid * 16 + q];
            wsum[tid] = ws;
        }
        __syncthreads();
        if (tid == 0) {
            unsigned total = 0;
            for (int l = 0; l < 32; ++l) total += wsum[l];
            unsigned K = total < TOPK ? total : TOPK;
            misc[6] = K;
            if (K > 0) {
                unsigned rem = K, cum = 0;
                int l = 31;
                for (;; --l) { unsigned v = wsum[l]; if (cum + v >= rem) break; cum += v; }
                int pp = l * 16 + 15;
                for (;; --pp) { unsigned v = part[pp]; if (cum + v >= rem) break; cum += v; }
                int bb = pp * 4 + 3;
                for (;; --bb) { unsigned v = hist[bb]; if (cum + v >= rem) break; cum += v; }
                unsigned take = rem - cum;
                misc[8] = (unsigned)bb;
                misc[4] = take;
                misc[11] = hist[bb];
                if (take == hist[bb]) {  // whole bin selected
                    misc[2] = (unsigned)bb << 21;
                    misc[3] = 0u;
                    misc[5] = 1u;
                }
            }
        }
        __syncthreads();
    }

    const int K = (int)misc[6];
    if (K == 0) {
        for (int e = tid; e < TOPK * 5; e += 512) outp[e] = 0.0f;
        return;
    }

    const unsigned bselA  = misc[8];
    const bool useList = (misc[11] <= LISTCAP);

    // ======== compact candidate keys of bin bselA into keyl ========
    if (!misc[5] && useList) {
        for (int j = tid; j < PNUM; j += 512) {
            float s = __ldg(&sp[j]);
            unsigned kb = __float_as_uint(s);
            bool m = (s > CONF_THV) && ((kb >> 21) == bselA);
            unsigned bal = __ballot_sync(0xFFFFFFFFu, m);
            unsigned base = 0;
            if ((tid & 31) == 0 && bal) base = atomicAdd(&misc[0], (unsigned)__popc(bal));
            base = __shfl_sync(0xFFFFFFFFu, base, 0);
            if (m) keyl[base + __popc(bal & ((1u << (tid & 31)) - 1u))] = kb;
        }
    }
    __syncthreads();

    // ======== PASS B: digit (key>>10)&0x7FF over list (or full scan) ========
    if (!misc[5]) {
        for (int h = tid; h < 2048; h += 512) hist[h] = 0u;
        __syncthreads();
        if (useList) {
            const int n = (int)misc[0];
            const int nup = (n + 511) & ~511;   // warp-uniform trip count
            for (int j = tid; j < nup; j += 512) {
                int bin = (j < n) ? (int)((keyl[j] >> 10) & 0x7FFu) : -1;
                unsigned grp = __match_any_sync(0xFFFFFFFFu, bin);
                if (((unsigned)tid & 31u) == (unsigned)(__ffs(grp) - 1) && bin >= 0)
                    atomicAdd(&hist[bin], (unsigned)__popc(grp));
            }
        } else {
            for (int j = tid; j < PNUM; j += 512) {
                float s = __ldg(&sp[j]);
                unsigned kb = __float_as_uint(s);
                int bin = (s > CONF_THV && (kb >> 21) == bselA)
                              ? (int)((kb >> 10) & 0x7FFu) : -1;
                unsigned grp = __match_any_sync(0xFFFFFFFFu, bin);
                if (((unsigned)tid & 31u) == (unsigned)(__ffs(grp) - 1) && bin >= 0)
                    atomicAdd(&hist[bin], (unsigned)__popc(grp));
            }
        }
        __syncthreads();
        unsigned s = hist[tid * 4] + hist[tid * 4 + 1] + hist[tid * 4 + 2] + hist[tid * 4 + 3];
        part[tid] = s;
        __syncthreads();
        if (tid < 32) {
            unsigned ws = 0;
            for (int q = 0; q < 16; ++q) ws += part[tid * 16 + q];
            wsum[tid] = ws;
        }
        __syncthreads();
        if (tid == 0) {
            unsigned rem = misc[4], cum = 0;
            int l = 31;
            for (;; --l) { unsigned v = wsum[l]; if (cum + v >= rem) break; cum += v; }
            int pp = l * 16 + 15;
            for (;; --pp) { unsigned v = part[pp]; if (cum + v >= rem) break; cum += v; }
            int bb = pp * 4 + 3;
            for (;; --bb) { unsigned v = hist[bb]; if (cum + v >= rem) break; cum += v; }
            unsigned take = rem - cum;
            unsigned pfx2 = (bselA << 11) | (unsigned)bb;
            misc[8] = pfx2;
            misc[4] = take;
            if (take == hist[bb]) {
                misc[2] = pfx2 << 10;
                misc[3] = 0u;
                misc[5] = 1u;
            }
        }
        __syncthreads();
    }

    // ======== PASS C: digit key&0x3FF (1024 bins) ========
    if (!misc[5]) {
        const unsigned pfx2 = misc[8];
        for (int h = tid; h < 1024; h += 512) hist[h] = 0u;
        __syncthreads();
        if (useList) {
            const int n = (int)misc[0];
            const int nup = (n + 511) & ~511;   // warp-uniform trip count
            for (int j = tid; j < nup; j += 512) {
                int bin = -1;
                if (j < n) {
                    unsigned kb = keyl[j];
                    if ((kb >> 10) == pfx2) bin = (int)(kb & 0x3FFu);
                }
                unsigned grp = __match_any_sync(0xFFFFFFFFu, bin);
                if (((unsigned)tid & 31u) == (unsigned)(__ffs(grp) - 1) && bin >= 0)
                    atomicAdd(&hist[bin], (unsigned)__popc(grp));
            }
        } else {
            for (int j = tid; j < PNUM; j += 512) {
                float s = __ldg(&sp[j]);
                unsigned kb = __float_as_uint(s);
                int bin = (s > CONF_THV && (kb >> 10) == pfx2) ? (int)(kb & 0x3FFu) : -1;
                unsigned grp = __match_any_sync(0xFFFFFFFFu, bin);
                if (((unsigned)tid & 31u) == (unsigned)(__ffs(grp) - 1) && bin >= 0)
                    atomicAdd(&hist[bin], (unsigned)__popc(grp));
            }
        }
        __syncthreads();
        unsigned s = hist[tid * 2] + hist[tid * 2 + 1];
        part[tid] = s;
        __syncthreads();
        if (tid < 32) {
            unsigned ws = 0;
            for (int q = 0; q < 16; ++q) ws += part[tid * 16 + q];
            wsum[tid] = ws;
        }
        __syncthreads();
        if (tid == 0) {
            unsigned rem = misc[4], cum = 0;
            int l = 31;
            for (;; --l) { unsigned v = wsum[l]; if (cum + v >= rem) break; cum += v; }
            int pp = l * 16 + 15;
            for (;; --pp) { unsigned v = part[pp]; if (cum + v >= rem) break; cum += v; }
            int bb = pp * 2 + 1;
            for (;; --bb) { unsigned v = hist[bb]; if (cum + v >= rem) break; cum += v; }
            unsigned take = rem - cum;
            misc[2] = (pfx2 << 10) | (unsigned)bb;
            if (take == hist[bb]) {
                misc[3] = 0u;
            } else {
                misc[3] = 1u;          // tie-split among exact-equal keys
                misc[13] = take;
            }
        }
        __syncthreads();
    }

    // ======== final compaction scan ========
    const unsigned THR = misc[2];
    const unsigned ntie = misc[3];
    for (int j = tid; j < PNUM; j += 512) {
        float s = __ldg(&sp[j]);
        unsigned kb = __float_as_uint(s);
        bool cand = (s > CONF_THV);
        bool sel = cand && (ntie ? (kb > THR) : (kb >= THR));
        unsigned bal = __ballot_sync(0xFFFFFFFFu, sel);
        unsigned base = 0;
        if ((tid & 31) == 0 && bal) base = atomicAdd(&misc[1], (unsigned)__popc(bal));
        base = __shfl_sync(0xFFFFFFFFu, base, 0);
        if (sel) {
            unsigned pos = base + __popc(bal & ((1u << (tid & 31)) - 1u));
            sel_s[pos] = s;
            sel_i[pos] = j;
        }
        if (ntie && cand && kb == THR) {
            unsigned p = atomicAdd(&misc[9], 1u);
            if (p < 512) eq[p] = (unsigned)j;
        }
    }
    __syncthreads();
    if (ntie && tid == 0) {
        int neq = (int)misc[9]; if (neq > 512) neq = 512;
        int take = (int)misc[13]; if (take > neq) take = neq;
        int base = (int)misc[1];
        for (int t = 0; t < take; ++t) {   // take smallest indices among equals
            unsigned best = 0xFFFFFFFFu; int bi = 0;
            for (int q = 0; q < neq; ++q)
                if (eq[q] < best) { best = eq[q]; bi = q; }
            eq[bi] = 0xFFFFFFFFu;
            sel_s[base + t] = __uint_as_float(THR);
            sel_i[base + t] = (int)best;
        }
        misc[1] = (unsigned)(base + take);
    }
    __syncthreads();
    if (tid >= K) { sel_s[tid] = -1.0f; sel_i[tid] = 0x40000000 + tid; }
    __syncthreads();

    // ======== bitonic sort 512: desc score, ties by smaller index ========
    for (unsigned k = 2; k <= 512; k <<= 1) {
        for (unsigned jj = k >> 1; jj > 0; jj >>= 1) {
            unsigned i = (unsigned)tid;
            unsigned ixj = i ^ jj;
            if (ixj > i) {
                float si = sel_s[i], sx = sel_s[ixj];
                int ii = sel_i[i], ix = sel_i[ixj];
                bool g = (sx > si) || (sx == si && ix < ii);
                bool asc = ((i & k) == 0);
                if (asc ? g : !g) {
                    sel_s[i] = sx; sel_s[ixj] = si;
                    sel_i[i] = ix; sel_i[ixj] = ii;
                }
            }
            __syncthreads();
        }
    }

    // ======== gather boxes ========
    {
        float4 bb = make_float4(0.f, 0.f, 0.f, 0.f);
        float a = 0.f;
        if (tid < K) {
            bb = g_boxes[(size_t)b * PNUM + sel_i[tid]];
            a = (bb.z - bb.x) * (bb.w - bb.y);
        }
        bx4[tid] = bb;
        s_area[tid] = a;
    }
    __syncthreads();

    // ======== upper-triangle suppression bitmatrix ========
    {
        const int w0 = tid >> 5;
        float4 bi = bx4[tid];
        float ai = s_area[tid];
        for (int w = w0; w < 16; ++w) {
            unsigned bits = 0u;
#pragma unroll 8
            for (int k = 0; k < 32; ++k) {
                int j = (w << 5) + k;
                float4 bj = bx4[j];
                float xx1 = fmaxf(bi.x, bj.x);
                float yy1 = fmaxf(bi.y, bj.y);
                float xx2 = fminf(bi.z, bj.z);
                float yy2 = fminf(bi.w, bj.w);
                float iw = fmaxf(xx2 - xx1, 0.0f);
                float ih = fmaxf(yy2 - yy1, 0.0f);
                float inter = iw * ih;
                float denom = (s_area[j] - inter) + ai;
                bool sup = !(inter <= NMS_THV * denom);
                bits |= (sup ? 1u : 0u) << k;
            }
            mat[tid * 16 + w] = bits;
        }
    }
    __syncthreads();

    // ======== monotonic NMS walk (single thread; pivots strictly increase) ====
    if (tid == 0) {
        unsigned* alive = &misc[16];
        for (int ww = 0; ww < 16; ++ww) {
            int n = K - ww * 32;
            alive[ww] = (n >= 32) ? 0xFFFFFFFFu : (n > 0 ? ((1u << n) - 1u) : 0u);
        }
        int cnt = 0;
        int w = 0;
        unsigned cur = alive[0];
        for (;;) {
            while (cur == 0u) {
                if (++w == 16) goto walk_done;
                cur = alive[w];
            }
            int bit = __ffs(cur) - 1;
            int pv = (w << 5) + bit;
            pord[cnt++] = pv;
            const unsigned* mrow = &mat[pv * 16];
            cur &= ~mrow[w];
            cur &= ~(1u << bit);
            for (int ww = w + 1; ww < 16; ++ww) alive[ww] &= ~mrow[ww];
        }
    walk_done:
        misc[7] = (unsigned)cnt;
    }
    __syncthreads();

    // ======== writeout ========
    const int cnt = (int)misc[7];
    for (int t = tid; t < TOPK; t += 512) {
        float r0 = 0.f, r1 = 0.f, r2 = 0.f, r3 = 0.f, r4 = 0.f;
        if (t < cnt) {
            int p = pord[t];
            float4 bb = bx4[p];
            r0 = sel_s[p]; r1 = bb.x; r2 = bb.y; r3 = bb.z; r4 = bb.w;
        }
        outp[t * 5 + 0] = r0;
        outp[t * 5 + 1] = r1;
        outp[t * 5 + 2] = r2;
        outp[t * 5 + 3] = r3;
        outp[t * 5 + 4] = r4;
    }
}

extern "C" void kernel_launch(void* const* d_in, const int* in_sizes, int n_in,
                              void* d_out, int out_size) {
    const float* arm_loc  = (const float*)d_in[0];
    const float* arm_conf = (const float*)d_in[1];
    const float* odm_loc  = (const float*)d_in[2];
    const float* odm_conf = (const float*)d_in[3];
    const float* priors   = (const float*)d_in[4];
    float* out = (float*)d_out;

    cudaFuncSetAttribute(task_kernel, cudaFuncAttributeMaxDynamicSharedMemorySize,
                         SMEM_TOTAL);

    int total = BATCH * PNUM;
    prep_kernel<<<(total + 255) / 256, 256>>>(arm_loc, arm_conf, odm_loc, odm_conf,
                                              priors);
    task_kernel<<<BATCH * NCLS, 512, SMEM_TOTAL>>>(out);
}

// round 6
// speedup vs baseline: 1.1730x; 1.1730x over previous
#include <cuda_runtime.h>

#define PNUM 16320
#define BATCH 32
#define NCLS 21
#define TOPK 500
#define CONF_THV 0.01f
#define NMS_THV 0.45f
#define OBJ_THV 0.01f
#define LISTCAP 4096

// ---- device scratch (no allocations allowed) ----
__device__ float4 g_boxes[BATCH * PNUM];                 // decoded boxes (x1,y1,x2,y2)
__device__ float  g_scores[BATCH * (NCLS - 1) * PNUM];   // arm-masked scores, [B][20][P]

// ---- shared memory layout (bytes) ----
#define OFF_MISC   0        // 128
#define OFF_SELS   128      // 512*4
#define OFF_SELI   2176     // 512*4
#define OFF_BOX    4224     // 512*16 (16B aligned)
#define OFF_AREA   12416    // 512*4
#define OFF_PORD   14464    // 512*4
#define OFF_MAT    16512    // 512*16*4 = 32768
#define SMEM_TOTAL 49280    // 4 blocks/SM (64 warps = max)
// overlays inside MAT (dead before matrix phase starts)
#define OFF_KEYL   16512    // 4096*4
#define OFF_HIST   32896    // 2048*4 (16B aligned)
#define OFF_PART   41088    // 512*4 part + 32*4 wsum
#define OFF_EQ     43264    // 512*4

// misc map: 0=nlist 1=ncomp 2=THR 3=need_tie 4=rem/take 5=done 6=K 7=cnt
//           8=prefix 9=neq 11=binCount 13=tieTake

// =====================================================================
// Kernel 1: cascaded decode + arm-masked score transpose
// =====================================================================
__global__ void prep_kernel(const float* __restrict__ arm_loc,
                            const float* __restrict__ arm_conf,
                            const float* __restrict__ odm_loc,
                            const float* __restrict__ odm_conf,
                            const float* __restrict__ priors) {
    int idx = blockIdx.x * blockDim.x + threadIdx.x;
    if (idx >= BATCH * PNUM) return;
    int b = idx / PNUM;
    int p = idx % PNUM;

    float pcx = priors[p * 4 + 0];
    float pcy = priors[p * 4 + 1];
    float pw  = priors[p * 4 + 2];
    float ph  = priors[p * 4 + 3];

    const float* al = arm_loc + (size_t)idx * 4;
    const float* ol = odm_loc + (size_t)idx * 4;

    float cx = pcx + al[0] * 0.1f * pw;
    float cy = pcy + al[1] * 0.1f * ph;
    float w  = pw * expf(al[2] * 0.2f);
    float h  = ph * expf(al[3] * 0.2f);
    float mnx = cx - w * 0.5f;
    float mny = cy - h * 0.5f;
    float mxx = mnx + w;
    float mxy = mny + h;
    float dcx = (mxx + mnx) * 0.5f;
    float dcy = (mxy + mny) * 0.5f;
    float dw  = mxx - mnx;
    float dh  = mxy - mny;

    float cx2 = dcx + ol[0] * 0.1f * dw;
    float cy2 = dcy + ol[1] * 0.1f * dh;
    float w2  = dw * expf(ol[2] * 0.2f);
    float h2  = dh * expf(ol[3] * 0.2f);
    float x1 = cx2 - w2 * 0.5f;
    float y1 = cy2 - h2 * 0.5f;
    float x2 = x1 + w2;
    float y2 = y1 + h2;
    g_boxes[idx] = make_float4(x1, y1, x2, y2);

    bool armpass = arm_conf[(size_t)idx * 2 + 1] > OBJ_THV;
    const float* oc = odm_conf + (size_t)idx * NCLS;
#pragma unroll
    for (int c = 1; c < NCLS; ++c) {
        float v = armpass ? oc[c] : 0.0f;
        g_scores[((size_t)(b * (NCLS - 1) + (c - 1))) * PNUM + p] = v;
    }
}

// =====================================================================
// Kernel 2: per (image,class): 32-bit radix select w/ list narrowing,
// bitonic sort, warp-per-row ballot-packed suppression bitmatrix,
// warp-parallel greedy NMS (alive bits in registers).
// =====================================================================
__global__ void __launch_bounds__(512) task_kernel(float* __restrict__ out) {
    extern __shared__ __align__(16) char smraw[];
    unsigned* misc   = (unsigned*)(smraw + OFF_MISC);
    float*    sel_s  = (float*)(smraw + OFF_SELS);
    int*      sel_i  = (int*)(smraw + OFF_SELI);
    float4*   bx4    = (float4*)(smraw + OFF_BOX);
    float*    s_area = (float*)(smraw + OFF_AREA);
    int*      pord   = (int*)(smraw + OFF_PORD);
    unsigned* mat    = (unsigned*)(smraw + OFF_MAT);
    unsigned* keyl   = (unsigned*)(smraw + OFF_KEYL);
    unsigned* hist   = (unsigned*)(smraw + OFF_HIST);
    unsigned* part   = (unsigned*)(smraw + OFF_PART);
    unsigned* wsum   = (unsigned*)(smraw + OFF_PART + 2048);
    unsigned* eq     = (unsigned*)(smraw + OFF_EQ);

    const int tid = threadIdx.x;
    const int b   = blockIdx.x / NCLS;
    const int cl  = blockIdx.x % NCLS;
    float* outp = out + (size_t)(b * NCLS + cl) * (TOPK * 5);

    if (cl == 0) {
        for (int e = tid; e < TOPK * 5; e += 512) outp[e] = 0.0f;
        return;
    }

    const float* __restrict__ sp =
        g_scores + (size_t)(b * (NCLS - 1) + (cl - 1)) * PNUM;

    // ======== PASS A: full-scan histogram on key>>21 (2048 bins) ========
    for (int h = tid; h < 2048; h += 512) hist[h] = 0u;
    if (tid < 16) misc[tid] = 0u;
    __syncthreads();

    for (int j = tid; j < PNUM; j += 512) {  // 16320 % 512 = 448 (warp-aligned)
        float s = __ldg(&sp[j]);
        int bin = (s > CONF_THV) ? (int)(__float_as_uint(s) >> 21) : -1;
        unsigned grp = __match_any_sync(0xFFFFFFFFu, bin);
        if (((unsigned)tid & 31u) == (unsigned)(__ffs(grp) - 1) && bin >= 0)
            atomicAdd(&hist[bin], (unsigned)__popc(grp));
    }
    __syncthreads();

    // parallel reduce + thread-0 search (includes total/K)
    {
        uint4 hv = ((const uint4*)hist)[tid];
        part[tid] = hv.x + hv.y + hv.z + hv.w;
        __syncthreads();
        if (tid < 32) {
            unsigned ws = 0;
            for (int q = 0; q < 16; ++q) ws += part[tid * 16 + q];
            wsum[tid] = ws;
        }
        __syncthreads();
        if (tid == 0) {
            unsigned total = 0;
            for (int l = 0; l < 32; ++l) total += wsum[l];
            unsigned K = total < TOPK ? total : TOPK;
            misc[6] = K;
            if (K > 0) {
                unsigned rem = K, cum = 0;
                int l = 31;
                for (;; --l) { unsigned v = wsum[l]; if (cum + v >= rem) break; cum += v; }
                int pp = l * 16 + 15;
                for (;; --pp) { unsigned v = part[pp]; if (cum + v >= rem) break; cum += v; }
                int bb = pp * 4 + 3;
                for (;; --bb) { unsigned v = hist[bb]; if (cum + v >= rem) break; cum += v; }
                unsigned take = rem - cum;
                misc[8] = (unsigned)bb;
                misc[4] = take;
                misc[11] = hist[bb];
                if (take == hist[bb]) {  // whole bin selected
                    misc[2] = (unsigned)bb << 21;
                    misc[3] = 0u;
                    misc[5] = 1u;
                }
            }
        }
        __syncthreads();
    }

    const int K = (int)misc[6];
    if (K == 0) {
        for (int e = tid; e < TOPK * 5; e += 512) outp[e] = 0.0f;
        return;
    }

    const unsigned bselA  = misc[8];
    const bool useList = (misc[11] <= LISTCAP);

    // ======== compact candidate keys of bin bselA into keyl ========
    if (!misc[5] && useList) {
        for (int j = tid; j < PNUM; j += 512) {
            float s = __ldg(&sp[j]);
            unsigned kb = __float_as_uint(s);
            bool m = (s > CONF_THV) && ((kb >> 21) == bselA);
            unsigned bal = __ballot_sync(0xFFFFFFFFu, m);
            unsigned base = 0;
            if ((tid & 31) == 0 && bal) base = atomicAdd(&misc[0], (unsigned)__popc(bal));
            base = __shfl_sync(0xFFFFFFFFu, base, 0);
            if (m) keyl[base + __popc(bal & ((1u << (tid & 31)) - 1u))] = kb;
        }
    }
    __syncthreads();

    // ======== PASS B: digit (key>>10)&0x7FF over list (or full scan) ========
    if (!misc[5]) {
        for (int h = tid; h < 2048; h += 512) hist[h] = 0u;
        __syncthreads();
        if (useList) {
            const int n = (int)misc[0];
            const int nup = (n + 511) & ~511;   // warp-uniform trip count
            for (int j = tid; j < nup; j += 512) {
                int bin = (j < n) ? (int)((keyl[j] >> 10) & 0x7FFu) : -1;
                unsigned grp = __match_any_sync(0xFFFFFFFFu, bin);
                if (((unsigned)tid & 31u) == (unsigned)(__ffs(grp) - 1) && bin >= 0)
                    atomicAdd(&hist[bin], (unsigned)__popc(grp));
            }
        } else {
            for (int j = tid; j < PNUM; j += 512) {
                float s = __ldg(&sp[j]);
                unsigned kb = __float_as_uint(s);
                int bin = (s > CONF_THV && (kb >> 21) == bselA)
                              ? (int)((kb >> 10) & 0x7FFu) : -1;
                unsigned grp = __match_any_sync(0xFFFFFFFFu, bin);
                if (((unsigned)tid & 31u) == (unsigned)(__ffs(grp) - 1) && bin >= 0)
                    atomicAdd(&hist[bin], (unsigned)__popc(grp));
            }
        }
        __syncthreads();
        uint4 hv = ((const uint4*)hist)[tid];
        part[tid] = hv.x + hv.y + hv.z + hv.w;
        __syncthreads();
        if (tid < 32) {
            unsigned ws = 0;
            for (int q = 0; q < 16; ++q) ws += part[tid * 16 + q];
            wsum[tid] = ws;
        }
        __syncthreads();
        if (tid == 0) {
            unsigned rem = misc[4], cum = 0;
            int l = 31;
            for (;; --l) { unsigned v = wsum[l]; if (cum + v >= rem) break; cum += v; }
            int pp = l * 16 + 15;
            for (;; --pp) { unsigned v = part[pp]; if (cum + v >= rem) break; cum += v; }
            int bb = pp * 4 + 3;
            for (;; --bb) { unsigned v = hist[bb]; if (cum + v >= rem) break; cum += v; }
            unsigned take = rem - cum;
            unsigned pfx2 = (bselA << 11) | (unsigned)bb;
            misc[8] = pfx2;
            misc[4] = take;
            if (take == hist[bb]) {
                misc[2] = pfx2 << 10;
                misc[3] = 0u;
                misc[5] = 1u;
            }
        }
        __syncthreads();
    }

    // ======== PASS C: digit key&0x3FF (1024 bins) ========
    if (!misc[5]) {
        const unsigned pfx2 = misc[8];
        for (int h = tid; h < 1024; h += 512) hist[h] = 0u;
        __syncthreads();
        if (useList) {
            const int n = (int)misc[0];
            const int nup = (n + 511) & ~511;   // warp-uniform trip count
            for (int j = tid; j < nup; j += 512) {
                int bin = -1;
                if (j < n) {
                    unsigned kb = keyl[j];
                    if ((kb >> 10) == pfx2) bin = (int)(kb & 0x3FFu);
                }
                unsigned grp = __match_any_sync(0xFFFFFFFFu, bin);
                if (((unsigned)tid & 31u) == (unsigned)(__ffs(grp) - 1) && bin >= 0)
                    atomicAdd(&hist[bin], (unsigned)__popc(grp));
            }
        } else {
            for (int j = tid; j < PNUM; j += 512) {
                float s = __ldg(&sp[j]);
                unsigned kb = __float_as_uint(s);
                int bin = (s > CONF_THV && (kb >> 10) == pfx2) ? (int)(kb & 0x3FFu) : -1;
                unsigned grp = __match_any_sync(0xFFFFFFFFu, bin);
                if (((unsigned)tid & 31u) == (unsigned)(__ffs(grp) - 1) && bin >= 0)
                    atomicAdd(&hist[bin], (unsigned)__popc(grp));
            }
        }
        __syncthreads();
        unsigned s = hist[tid * 2] + hist[tid * 2 + 1];
        part[tid] = s;
        __syncthreads();
        if (tid < 32) {
            unsigned ws = 0;
            for (int q = 0; q < 16; ++q) ws += part[tid * 16 + q];
            wsum[tid] = ws;
        }
        __syncthreads();
        if (tid == 0) {
            unsigned rem = misc[4], cum = 0;
            int l = 31;
            for (;; --l) { unsigned v = wsum[l]; if (cum + v >= rem) break; cum += v; }
            int pp = l * 16 + 15;
            for (;; --pp) { unsigned v = part[pp]; if (cum + v >= rem) break; cum += v; }
            int bb = pp * 2 + 1;
            for (;; --bb) { unsigned v = hist[bb]; if (cum + v >= rem) break; cum += v; }
            unsigned take = rem - cum;
            misc[2] = (pfx2 << 10) | (unsigned)bb;
            if (take == hist[bb]) {
                misc[3] = 0u;
            } else {
                misc[3] = 1u;          // tie-split among exact-equal keys
                misc[13] = take;
            }
        }
        __syncthreads();
    }

    // ======== final compaction scan ========
    const unsigned THR = misc[2];
    const unsigned ntie = misc[3];
    for (int j = tid; j < PNUM; j += 512) {
        float s = __ldg(&sp[j]);
        unsigned kb = __float_as_uint(s);
        bool cand = (s > CONF_THV);
        bool sel = cand && (ntie ? (kb > THR) : (kb >= THR));
        unsigned bal = __ballot_sync(0xFFFFFFFFu, sel);
        unsigned base = 0;
        if ((tid & 31) == 0 && bal) base = atomicAdd(&misc[1], (unsigned)__popc(bal));
        base = __shfl_sync(0xFFFFFFFFu, base, 0);
        if (sel) {
            unsigned pos = base + __popc(bal & ((1u << (tid & 31)) - 1u));
            sel_s[pos] = s;
            sel_i[pos] = j;
        }
        if (ntie && cand && kb == THR) {
            unsigned p = atomicAdd(&misc[9], 1u);
            if (p < 512) eq[p] = (unsigned)j;
        }
    }
    __syncthreads();
    if (ntie && tid == 0) {
        int neq = (int)misc[9]; if (neq > 512) neq = 512;
        int take = (int)misc[13]; if (take > neq) take = neq;
        int base = (int)misc[1];
        for (int t = 0; t < take; ++t) {   // take smallest indices among equals
            unsigned best = 0xFFFFFFFFu; int bi = 0;
            for (int q = 0; q < neq; ++q)
                if (eq[q] < best) { best = eq[q]; bi = q; }
            eq[bi] = 0xFFFFFFFFu;
            sel_s[base + t] = __uint_as_float(THR);
            sel_i[base + t] = (int)best;
        }
        misc[1] = (unsigned)(base + take);
    }
    __syncthreads();
    if (tid >= K) { sel_s[tid] = -1.0f; sel_i[tid] = 0x40000000 + tid; }
    __syncthreads();

    // ======== bitonic sort 512: desc score, ties by smaller index ========
    for (unsigned k = 2; k <= 512; k <<= 1) {
        for (unsigned jj = k >> 1; jj > 0; jj >>= 1) {
            unsigned i = (unsigned)tid;
            unsigned ixj = i ^ jj;
            if (ixj > i) {
                float si = sel_s[i], sx = sel_s[ixj];
                int ii = sel_i[i], ix = sel_i[ixj];
                bool g = (sx > si) || (sx == si && ix < ii);
                bool asc = ((i & k) == 0);
                if (asc ? g : !g) {
                    sel_s[i] = sx; sel_s[ixj] = si;
                    sel_i[i] = ix; sel_i[ixj] = ii;
                }
            }
            __syncthreads();
        }
    }

    // ======== gather boxes ========
    {
        float4 bb = make_float4(0.f, 0.f, 0.f, 0.f);
        float a = 0.f;
        if (tid < K) {
            bb = g_boxes[(size_t)b * PNUM + sel_i[tid]];
            a = (bb.z - bb.x) * (bb.w - bb.y);
        }
        bx4[tid] = bb;
        s_area[tid] = a;
    }
    __syncthreads();

    // ======== upper-triangle suppression bitmatrix (warp-per-row, ballot) ====
    {
        const int wid  = tid >> 5;
        const int lane = tid & 31;
        for (int r = wid; r < 512; r += 16) {     // r uniform within warp
            float4 bi = bx4[r];                   // broadcast LDS
            float ai = s_area[r];
            for (int w = r >> 5; w < 16; ++w) {
                int j = (w << 5) + lane;
                float4 bj = bx4[j];
                float xx1 = fmaxf(bi.x, bj.x);
                float yy1 = fmaxf(bi.y, bj.y);
                float xx2 = fminf(bi.z, bj.z);
                float yy2 = fminf(bi.w, bj.w);
                float iw = fmaxf(xx2 - xx1, 0.0f);
                float ih = fmaxf(yy2 - yy1, 0.0f);
                float inter = iw * ih;
                float denom = (s_area[j] - inter) + ai;   // union; > 0 for real boxes
                bool sup = !(inter <= NMS_THV * denom);   // == !(iou <= TH)
                unsigned bits = __ballot_sync(0xFFFFFFFFu, sup);
                if (lane == 0) mat[r * 16 + w] = bits;
            }
        }
    }
    __syncthreads();

    // ======== greedy NMS: warp 0, alive bits in registers ========
    // Lower-triangle mat words are garbage, but harmless: the pivot is the
    // first alive bit, so all am bits below it are already 0 and AND-clear
    // cannot set bits.
    if (tid < 32) {
        unsigned am = 0u;
        if (tid < 16) {
            int n = K - tid * 32;
            am = (n >= 32) ? 0xFFFFFFFFu : (n > 0 ? ((1u << n) - 1u) : 0u);
        }
        int cnt = 0;
        for (int t = 0; t < TOPK; ++t) {
            unsigned bal = __ballot_sync(0xFFFFFFFFu, am != 0u);
            if (!bal) break;
            int wsel = __ffs(bal) - 1;
            unsigned word = __shfl_sync(0xFFFFFFFFu, am, wsel);
            int pv = (wsel << 5) + __ffs(word) - 1;
            if (tid == 0) pord[t] = pv;
            cnt = t + 1;
            unsigned mrow = (tid < 16) ? mat[pv * 16 + tid] : 0u;
            am &= ~mrow;
            if (tid == wsel) am &= ~(1u << (pv & 31));
        }
        if (tid == 0) misc[7] = (unsigned)cnt;
    }
    __syncthreads();

    // ======== writeout ========
    const int cnt = (int)misc[7];
    for (int t = tid; t < TOPK; t += 512) {
        float r0 = 0.f, r1 = 0.f, r2 = 0.f, r3 = 0.f, r4 = 0.f;
        if (t < cnt) {
            int p = pord[t];
            float4 bb = bx4[p];
            r0 = sel_s[p]; r1 = bb.x; r2 = bb.y; r3 = bb.z; r4 = bb.w;
        }
        outp[t * 5 + 0] = r0;
        outp[t * 5 + 1] = r1;
        outp[t * 5 + 2] = r2;
        outp[t * 5 + 3] = r3;
        outp[t * 5 + 4] = r4;
    }
}

extern "C" void kernel_launch(void* const* d_in, const int* in_sizes, int n_in,
                              void* d_out, int out_size) {
    const float* arm_loc  = (const float*)d_in[0];
    const float* arm_conf = (const float*)d_in[1];
    const float* odm_loc  = (const float*)d_in[2];
    const float* odm_conf = (const float*)d_in[3];
    const float* priors   = (const float*)d_in[4];
    float* out = (float*)d_out;

    cudaFuncSetAttribute(task_kernel, cudaFuncAttributeMaxDynamicSharedMemorySize,
                         SMEM_TOTAL);

    int total = BATCH * PNUM;
    prep_kernel<<<(total + 255) / 256, 256>>>(arm_loc, arm_conf, odm_loc, odm_conf,
                                              priors);
    task_kernel<<<BATCH * NCLS, 512, SMEM_TOTAL>>>(out);
}

// round 7
// speedup vs baseline: 1.4677x; 1.2512x over previous
#include <cuda_runtime.h>

#define PNUM 16320
#define BATCH 32
#define NCLS 21
#define TOPK 500
#define CONF_THV 0.01f
#define NMS_THV 0.45f
#define OBJ_THV 0.01f
#define NT 256

// ---- device scratch (no allocations allowed) ----
__device__ float4 g_boxes[BATCH * PNUM];                 // decoded boxes (x1,y1,x2,y2)
__device__ float  g_scores[BATCH * (NCLS - 1) * PNUM];   // arm-masked scores, [B][20][P]

// ---- shared memory layout (bytes) ----
#define OFF_MISC   0        // 64 (16 u32)
#define OFF_SELS   64       // 512*4 = 2048
#define OFF_SELI   2112     // 2048
#define OFF_BOX    4160     // 512*16 = 8192 (16B aligned)
#define OFF_AREA   12352    // 2048
#define OFF_PORD   14400    // 2048
#define OFF_MAT    16448    // triangle-packed 4352 words = 17408
#define SMEM_TOTAL 33856    // -> 6 blocks/SM; 672 blocks fit in ONE wave
// overlays inside MAT (dead until matrix phase)
#define OFF_HIST   16448    // 256*4
#define OFF_WSUM   17472    // 8*4

// misc: 1=ncomp 2=THRlo 3=THRhi 4=rem 5=done 6=K 7=cnt

// triangle packing: rows grouped by block rb=r>>5; row r stores words rb..15
__host__ __device__ __forceinline__ int tri_base(int rb) {
    return 32 * (16 * rb) - 16 * rb * (rb - 1);  // 32*(16*rb - rb*(rb-1)/2)
}

// =====================================================================
// Kernel 1: cascaded decode + arm-masked score transpose
// =====================================================================
__global__ void prep_kernel(const float* __restrict__ arm_loc,
                            const float* __restrict__ arm_conf,
                            const float* __restrict__ odm_loc,
                            const float* __restrict__ odm_conf,
                            const float* __restrict__ priors) {
    int idx = blockIdx.x * blockDim.x + threadIdx.x;
    if (idx >= BATCH * PNUM) return;
    int b = idx / PNUM;
    int p = idx % PNUM;

    float pcx = priors[p * 4 + 0];
    float pcy = priors[p * 4 + 1];
    float pw  = priors[p * 4 + 2];
    float ph  = priors[p * 4 + 3];

    const float* al = arm_loc + (size_t)idx * 4;
    const float* ol = odm_loc + (size_t)idx * 4;

    float cx = pcx + al[0] * 0.1f * pw;
    float cy = pcy + al[1] * 0.1f * ph;
    float w  = pw * expf(al[2] * 0.2f);
    float h  = ph * expf(al[3] * 0.2f);
    float mnx = cx - w * 0.5f;
    float mny = cy - h * 0.5f;
    float mxx = mnx + w;
    float mxy = mny + h;
    float dcx = (mxx + mnx) * 0.5f;
    float dcy = (mxy + mny) * 0.5f;
    float dw  = mxx - mnx;
    float dh  = mxy - mny;

    float cx2 = dcx + ol[0] * 0.1f * dw;
    float cy2 = dcy + ol[1] * 0.1f * dh;
    float w2  = dw * expf(ol[2] * 0.2f);
    float h2  = dh * expf(ol[3] * 0.2f);
    float x1 = cx2 - w2 * 0.5f;
    float y1 = cy2 - h2 * 0.5f;
    float x2 = x1 + w2;
    float y2 = y1 + h2;
    g_boxes[idx] = make_float4(x1, y1, x2, y2);

    bool armpass = arm_conf[(size_t)idx * 2 + 1] > OBJ_THV;
    const float* oc = odm_conf + (size_t)idx * NCLS;
#pragma unroll
    for (int c = 1; c < NCLS; ++c) {
        float v = armpass ? oc[c] : 0.0f;
        g_scores[((size_t)(b * (NCLS - 1) + (c - 1))) * PNUM + p] = v;
    }
}

// =====================================================================
// Kernel 2: per (image,class), 256 threads. 64-bit byte-radix top-K
// (exact lax.top_k tie semantics via score||~index key), bitonic sort,
// triangle-packed ballot suppression matrix, register-resident serial
// NMS walk.
// =====================================================================
__global__ void __launch_bounds__(NT) task_kernel(float* __restrict__ out) {
    extern __shared__ __align__(16) char smraw[];
    unsigned* misc   = (unsigned*)(smraw + OFF_MISC);
    float*    sel_s  = (float*)(smraw + OFF_SELS);
    int*      sel_i  = (int*)(smraw + OFF_SELI);
    float4*   bx4    = (float4*)(smraw + OFF_BOX);
    float*    s_area = (float*)(smraw + OFF_AREA);
    int*      pord   = (int*)(smraw + OFF_PORD);
    unsigned* mat    = (unsigned*)(smraw + OFF_MAT);
    unsigned* hist   = (unsigned*)(smraw + OFF_HIST);
    unsigned* wsum   = (unsigned*)(smraw + OFF_WSUM);

    const int tid = threadIdx.x;
    const int b   = blockIdx.x / NCLS;
    const int cl  = blockIdx.x % NCLS;
    float* outp = out + (size_t)(b * NCLS + cl) * (TOPK * 5);

    if (cl == 0) {  // background class: all zeros
        for (int e = tid; e < TOPK * 5; e += NT) outp[e] = 0.0f;
        return;
    }

    const float* __restrict__ sp =
        g_scores + (size_t)(b * (NCLS - 1) + (cl - 1)) * PNUM;

    // ======== PASS A: byte 7 histogram (= top score byte) + total ========
    hist[tid] = 0u;                  // NT==256 bins exactly
    if (tid < 16) misc[tid] = 0u;
    __syncthreads();

    for (int j = tid; j < PNUM; j += NT) {   // 16320%256=192=6 warps: warp-uniform
        float s = __ldg(&sp[j]);
        int bin = (s > CONF_THV) ? (int)(__float_as_uint(s) >> 24) : 256;
        unsigned grp = __match_any_sync(0xFFFFFFFFu, bin);
        if (((unsigned)tid & 31u) == (unsigned)(__ffs(grp) - 1) && bin < 256)
            atomicAdd(&hist[bin], (unsigned)__popc(grp));
    }
    __syncthreads();
    {   // warp-reduce histogram -> 8 partials
        unsigned v = hist[tid];
#pragma unroll
        for (int o = 16; o; o >>= 1) v += __shfl_down_sync(0xFFFFFFFFu, v, o);
        if ((tid & 31) == 0) wsum[tid >> 5] = v;
    }
    __syncthreads();
    if (tid == 0) {
        unsigned total = 0;
        for (int l = 0; l < 8; ++l) total += wsum[l];
        unsigned K = total < TOPK ? total : TOPK;
        misc[6] = K;
        if (K > 0) {
            unsigned rem = K, cum = 0;
            int l = 7;
            for (;; --l) { unsigned v = wsum[l]; if (cum + v >= rem) break; cum += v; }
            int bb = l * 32 + 31;
            for (;; --bb) { unsigned v = hist[bb]; if (cum + v >= rem) break; cum += v; }
            unsigned take = rem - cum;
            unsigned long long pfx = (unsigned long long)bb << 56;
            misc[2] = (unsigned)pfx;
            misc[3] = (unsigned)(pfx >> 32);
            misc[4] = take;
            if (take == hist[bb]) misc[5] = 1u;
        }
    }
    __syncthreads();

    const int K = (int)misc[6];
    if (K == 0) {
        for (int e = tid; e < TOPK * 5; e += NT) outp[e] = 0.0f;
        return;
    }

    // ======== remaining byte passes ========
    for (int bp = 6; bp >= 0; --bp) {
        if (misc[5]) break;          // uniform (read post-sync)
        hist[tid] = 0u;
        __syncthreads();
        unsigned long long pfx = ((unsigned long long)misc[3] << 32) | misc[2];
        for (int j = tid; j < PNUM; j += NT) {
            float s = __ldg(&sp[j]);
            int bin = 256;
            if (s > CONF_THV) {
                unsigned long long key =
                    ((unsigned long long)__float_as_uint(s) << 32) |
                    (unsigned long long)(0xFFFFFFFFu - (unsigned)j);
                if ((key >> ((bp + 1) * 8)) == (pfx >> ((bp + 1) * 8)))
                    bin = (int)((key >> (bp * 8)) & 0xFFull);
            }
            unsigned grp = __match_any_sync(0xFFFFFFFFu, bin);
            if (((unsigned)tid & 31u) == (unsigned)(__ffs(grp) - 1) && bin < 256)
                atomicAdd(&hist[bin], (unsigned)__popc(grp));
        }
        __syncthreads();
        {
            unsigned v = hist[tid];
#pragma unroll
            for (int o = 16; o; o >>= 1) v += __shfl_down_sync(0xFFFFFFFFu, v, o);
            if ((tid & 31) == 0) wsum[tid >> 5] = v;
        }
        __syncthreads();
        if (tid == 0) {
            unsigned rem = misc[4], cum = 0;
            int l = 7;
            for (;; --l) { unsigned v = wsum[l]; if (cum + v >= rem) break; cum += v; }
            int bb = l * 32 + 31;
            for (;; --bb) { unsigned v = hist[bb]; if (cum + v >= rem) break; cum += v; }
            unsigned take = rem - cum;
            unsigned long long pfx2 = (((unsigned long long)misc[3] << 32) | misc[2]) |
                                      ((unsigned long long)bb << (bp * 8));
            misc[2] = (unsigned)pfx2;
            misc[3] = (unsigned)(pfx2 >> 32);
            misc[4] = take;
            if (take == hist[bb]) misc[5] = 1u;
        }
        __syncthreads();
    }
    __syncthreads();
    const unsigned long long T = ((unsigned long long)misc[3] << 32) | misc[2];

    // ======== compact the exactly-K selected keys ========
    for (int j = tid; j < PNUM; j += NT) {
        float s = __ldg(&sp[j]);
        bool sel = false;
        if (s > CONF_THV) {
            unsigned long long key =
                ((unsigned long long)__float_as_uint(s) << 32) |
                (unsigned long long)(0xFFFFFFFFu - (unsigned)j);
            sel = (key >= T);
        }
        unsigned m = __ballot_sync(0xFFFFFFFFu, sel);
        unsigned base = 0;
        if ((tid & 31) == 0 && m) base = atomicAdd(&misc[1], (unsigned)__popc(m));
        base = __shfl_sync(0xFFFFFFFFu, base, 0);
        if (sel) {
            unsigned pos = base + __popc(m & ((1u << (tid & 31)) - 1u));
            sel_s[pos] = s;
            sel_i[pos] = j;
        }
    }
    __syncthreads();
    for (int i = tid; i < 512; i += NT)
        if (i >= K) { sel_s[i] = -1.0f; sel_i[i] = 0x40000000 + i; }
    __syncthreads();

    // ======== bitonic sort 512 (2 elems/thread): desc, ties smaller idx ======
    for (unsigned k = 2; k <= 512; k <<= 1) {
        for (unsigned jj = k >> 1; jj > 0; jj >>= 1) {
#pragma unroll
            for (int half = 0; half < 512; half += NT) {
                unsigned i = (unsigned)(half + tid);
                unsigned ixj = i ^ jj;
                if (ixj > i) {
                    float si = sel_s[i], sx = sel_s[ixj];
                    int ii = sel_i[i], ix = sel_i[ixj];
                    bool g = (sx > si) || (sx == si && ix < ii);
                    bool asc = ((i & k) == 0);
                    if (asc ? g : !g) {
                        sel_s[i] = sx; sel_s[ixj] = si;
                        sel_i[i] = ix; sel_i[ixj] = ii;
                    }
                }
            }
            __syncthreads();
        }
    }

    // ======== gather boxes ========
    for (int i = tid; i < 512; i += NT) {
        float4 bb = make_float4(0.f, 0.f, 0.f, 0.f);
        float a = 0.f;
        if (i < K) {
            bb = g_boxes[(size_t)b * PNUM + sel_i[i]];
            a = (bb.z - bb.x) * (bb.w - bb.y);
        }
        bx4[i] = bb;
        s_area[i] = a;
    }
    __syncthreads();

    // ======== triangle-packed suppression bitmatrix (warp-per-row) ========
    {
        const int wid  = tid >> 5;
        const int lane = tid & 31;
        for (int r = wid; r < 512; r += 8) {         // r uniform within warp
            float4 bi = bx4[r];
            float ai = s_area[r];
            int rb = r >> 5;
            int base = tri_base(rb) + (r & 31) * (16 - rb);
            for (int w = rb; w < 16; ++w) {
                int j = (w << 5) + lane;
                float4 bj = bx4[j];
                float xx1 = fmaxf(bi.x, bj.x);
                float yy1 = fmaxf(bi.y, bj.y);
                float xx2 = fminf(bi.z, bj.z);
                float yy2 = fminf(bi.w, bj.w);
                float iw = fmaxf(xx2 - xx1, 0.0f);
                float ih = fmaxf(yy2 - yy1, 0.0f);
                float inter = iw * ih;
                float denom = (s_area[j] - inter) + ai;  // union; > 0 for real boxes
                bool sup = !(inter <= NMS_THV * denom);  // == !(iou <= TH)
                unsigned bits = __ballot_sync(0xFFFFFFFFu, sup);
                if (lane == 0) mat[base + (w - rb)] = bits;
            }
        }
    }
    __syncthreads();

    // ======== greedy NMS walk: ONE thread, alive[16] in REGISTERS ========
    // Pivots strictly increase on a sorted list; packed row of pivot pv
    // (block W=pv>>5) holds words W..15. Self bit clears via its own row
    // (iou(pv,pv)=1 > TH).
    if (tid == 0) {
        unsigned alive[16];
#pragma unroll
        for (int ww = 0; ww < 16; ++ww) {
            int n = K - ww * 32;
            alive[ww] = (n >= 32) ? 0xFFFFFFFFu : (n > 0 ? ((1u << n) - 1u) : 0u);
        }
        int cnt = 0;
#pragma unroll
        for (int W = 0; W < 16; ++W) {
            const int nw = 16 - W;
            const unsigned* blk = mat + tri_base(W);
            unsigned cur = alive[W];
            while (cur) {
                int bit = __ffs(cur) - 1;
                pord[cnt++] = (W << 5) + bit;
                const unsigned* mrow = blk + bit * nw;
                cur &= ~mrow[0];
#pragma unroll
                for (int ww = W + 1; ww < 16; ++ww)
                    alive[ww] &= ~mrow[ww - W];
            }
        }
        misc[7] = (unsigned)cnt;
    }
    __syncthreads();

    // ======== writeout ========
    const int cnt = (int)misc[7];
    for (int t = tid; t < TOPK; t += NT) {
        float r0 = 0.f, r1 = 0.f, r2 = 0.f, r3 = 0.f, r4 = 0.f;
        if (t < cnt) {
            int p = pord[t];
            float4 bb = bx4[p];
            r0 = sel_s[p]; r1 = bb.x; r2 = bb.y; r3 = bb.z; r4 = bb.w;
        }
        outp[t * 5 + 0] = r0;
        outp[t * 5 + 1] = r1;
        outp[t * 5 + 2] = r2;
        outp[t * 5 + 3] = r3;
        outp[t * 5 + 4] = r4;
    }
}

extern "C" void kernel_launch(void* const* d_in, const int* in_sizes, int n_in,
                              void* d_out, int out_size) {
    const float* arm_loc  = (const float*)d_in[0];
    const float* arm_conf = (const float*)d_in[1];
    const float* odm_loc  = (const float*)d_in[2];
    const float* odm_conf = (const float*)d_in[3];
    const float* priors   = (const float*)d_in[4];
    float* out = (float*)d_out;

    cudaFuncSetAttribute(task_kernel, cudaFuncAttributeMaxDynamicSharedMemorySize,
                         SMEM_TOTAL);

    int total = BATCH * PNUM;
    prep_kernel<<<(total + 255) / 256, 256>>>(arm_loc, arm_conf, odm_loc, odm_conf,
                                              priors);
    task_kernel<<<BATCH * NCLS, NT, SMEM_TOTAL>>>(out);
}

// round 8
// speedup vs baseline: 1.5412x; 1.0501x over previous
#include <cuda_runtime.h>

#define PNUM 16320
#define BATCH 32
#define NCLS 21
#define TOPK 500
#define CONF_THV 0.01f
#define NMS_THV 0.45f
#define OBJ_THV 0.01f
#define NT 256
// TH/(1+TH) for the transformed suppression test
#define NMS_COEF 0.310344827586206896f

// ---- device scratch (no allocations allowed) ----
__device__ float4 g_boxes[BATCH * PNUM];                 // decoded boxes (x1,y1,x2,y2)
__device__ float  g_scores[BATCH * (NCLS - 1) * PNUM];   // arm-masked scores, [B][20][P]

// ---- shared memory layout (bytes) ----
#define OFF_MISC   0        // 64 (16 u32)
#define OFF_SELS   64       // 512*4 = 2048
#define OFF_SELI   2112     // 2048
#define OFF_BOX    4160     // 512*16 = 8192 (16B aligned)
#define OFF_AREA   12352    // 2048  (holds c_i = NMS_COEF * area_i)
#define OFF_PORD   14400    // 2048
#define OFF_MAT    16448    // triangle-packed 4352 words = 17408
#define SMEM_TOTAL 33856    // -> 6 blocks/SM; 672 blocks in ONE wave
// overlays inside MAT (dead until matrix phase)
#define OFF_HIST   16448    // 256*4
#define OFF_WSUM   17472    // 8*4

// misc: 1=ncomp 2=THRlo 3=THRhi 4=rem 5=done 6=K 7=cnt

// triangle packing: rows grouped by block rb=r>>5; row r stores words rb..15
__host__ __device__ __forceinline__ int tri_base(int rb) {
    return 32 * (16 * rb) - 16 * rb * (rb - 1);  // 32*(16*rb - rb*(rb-1)/2)
}

// =====================================================================
// Kernel 1: cascaded decode + arm-masked score transpose
// =====================================================================
__global__ void prep_kernel(const float* __restrict__ arm_loc,
                            const float* __restrict__ arm_conf,
                            const float* __restrict__ odm_loc,
                            const float* __restrict__ odm_conf,
                            const float* __restrict__ priors) {
    int idx = blockIdx.x * blockDim.x + threadIdx.x;
    if (idx >= BATCH * PNUM) return;
    int b = idx / PNUM;
    int p = idx % PNUM;

    float pcx = priors[p * 4 + 0];
    float pcy = priors[p * 4 + 1];
    float pw  = priors[p * 4 + 2];
    float ph  = priors[p * 4 + 3];

    const float* al = arm_loc + (size_t)idx * 4;
    const float* ol = odm_loc + (size_t)idx * 4;

    float cx = pcx + al[0] * 0.1f * pw;
    float cy = pcy + al[1] * 0.1f * ph;
    float w  = pw * expf(al[2] * 0.2f);
    float h  = ph * expf(al[3] * 0.2f);
    float mnx = cx - w * 0.5f;
    float mny = cy - h * 0.5f;
    float mxx = mnx + w;
    float mxy = mny + h;
    float dcx = (mxx + mnx) * 0.5f;
    float dcy = (mxy + mny) * 0.5f;
    float dw  = mxx - mnx;
    float dh  = mxy - mny;

    float cx2 = dcx + ol[0] * 0.1f * dw;
    float cy2 = dcy + ol[1] * 0.1f * dh;
    float w2  = dw * expf(ol[2] * 0.2f);
    float h2  = dh * expf(ol[3] * 0.2f);
    float x1 = cx2 - w2 * 0.5f;
    float y1 = cy2 - h2 * 0.5f;
    float x2 = x1 + w2;
    float y2 = y1 + h2;
    g_boxes[idx] = make_float4(x1, y1, x2, y2);

    bool armpass = arm_conf[(size_t)idx * 2 + 1] > OBJ_THV;
    const float* oc = odm_conf + (size_t)idx * NCLS;
#pragma unroll
    for (int c = 1; c < NCLS; ++c) {
        float v = armpass ? oc[c] : 0.0f;
        g_scores[((size_t)(b * (NCLS - 1) + (c - 1))) * PNUM + p] = v;
    }
}

// =====================================================================
// Kernel 2: per (image,class), 256 threads. 64-bit byte-radix top-K
// (exact lax.top_k tie semantics), bitonic sort, column-strip triangle
// suppression matrix (bj/cj register-resident), register-resident walk.
// =====================================================================
__global__ void __launch_bounds__(NT) task_kernel(float* __restrict__ out) {
    extern __shared__ __align__(16) char smraw[];
    unsigned* misc   = (unsigned*)(smraw + OFF_MISC);
    float*    sel_s  = (float*)(smraw + OFF_SELS);
    int*      sel_i  = (int*)(smraw + OFF_SELI);
    float4*   bx4    = (float4*)(smraw + OFF_BOX);
    float*    s_c    = (float*)(smraw + OFF_AREA);
    int*      pord   = (int*)(smraw + OFF_PORD);
    unsigned* mat    = (unsigned*)(smraw + OFF_MAT);
    unsigned* hist   = (unsigned*)(smraw + OFF_HIST);
    unsigned* wsum   = (unsigned*)(smraw + OFF_WSUM);

    const int tid = threadIdx.x;
    const int b   = blockIdx.x / NCLS;
    const int cl  = blockIdx.x % NCLS;
    float* outp = out + (size_t)(b * NCLS + cl) * (TOPK * 5);

    if (cl == 0) {  // background class: all zeros
        for (int e = tid; e < TOPK * 5; e += NT) outp[e] = 0.0f;
        return;
    }

    const float* __restrict__ sp =
        g_scores + (size_t)(b * (NCLS - 1) + (cl - 1)) * PNUM;

    // ======== PASS A: byte 7 histogram (= top score byte) + total ========
    hist[tid] = 0u;                  // NT==256 bins exactly
    if (tid < 16) misc[tid] = 0u;
    __syncthreads();

    for (int j = tid; j < PNUM; j += NT) {   // 16320%256=192: warp-uniform split
        float s = __ldg(&sp[j]);
        int bin = (s > CONF_THV) ? (int)(__float_as_uint(s) >> 24) : 256;
        unsigned grp = __match_any_sync(0xFFFFFFFFu, bin);
        if (((unsigned)tid & 31u) == (unsigned)(__ffs(grp) - 1) && bin < 256)
            atomicAdd(&hist[bin], (unsigned)__popc(grp));
    }
    __syncthreads();
    {   // warp-reduce histogram -> 8 partials
        unsigned v = hist[tid];
#pragma unroll
        for (int o = 16; o; o >>= 1) v += __shfl_down_sync(0xFFFFFFFFu, v, o);
        if ((tid & 31) == 0) wsum[tid >> 5] = v;
    }
    __syncthreads();
    if (tid == 0) {
        unsigned total = 0;
        for (int l = 0; l < 8; ++l) total += wsum[l];
        unsigned K = total < TOPK ? total : TOPK;
        misc[6] = K;
        if (K > 0) {
            unsigned rem = K, cum = 0;
            int l = 7;
            for (;; --l) { unsigned v = wsum[l]; if (cum + v >= rem) break; cum += v; }
            int bb = l * 32 + 31;
            for (;; --bb) { unsigned v = hist[bb]; if (cum + v >= rem) break; cum += v; }
            unsigned take = rem - cum;
            unsigned long long pfx = (unsigned long long)bb << 56;
            misc[2] = (unsigned)pfx;
            misc[3] = (unsigned)(pfx >> 32);
            misc[4] = take;
            if (take == hist[bb]) misc[5] = 1u;
        }
    }
    __syncthreads();

    const int K = (int)misc[6];
    if (K == 0) {
        for (int e = tid; e < TOPK * 5; e += NT) outp[e] = 0.0f;
        return;
    }

    // ======== remaining byte passes ========
    for (int bp = 6; bp >= 0; --bp) {
        if (misc[5]) break;          // uniform (read post-sync)
        hist[tid] = 0u;
        __syncthreads();
        unsigned long long pfx = ((unsigned long long)misc[3] << 32) | misc[2];
        for (int j = tid; j < PNUM; j += NT) {
            float s = __ldg(&sp[j]);
            int bin = 256;
            if (s > CONF_THV) {
                unsigned long long key =
                    ((unsigned long long)__float_as_uint(s) << 32) |
                    (unsigned long long)(0xFFFFFFFFu - (unsigned)j);
                if ((key >> ((bp + 1) * 8)) == (pfx >> ((bp + 1) * 8)))
                    bin = (int)((key >> (bp * 8)) & 0xFFull);
            }
            unsigned grp = __match_any_sync(0xFFFFFFFFu, bin);
            if (((unsigned)tid & 31u) == (unsigned)(__ffs(grp) - 1) && bin < 256)
                atomicAdd(&hist[bin], (unsigned)__popc(grp));
        }
        __syncthreads();
        {
            unsigned v = hist[tid];
#pragma unroll
            for (int o = 16; o; o >>= 1) v += __shfl_down_sync(0xFFFFFFFFu, v, o);
            if ((tid & 31) == 0) wsum[tid >> 5] = v;
        }
        __syncthreads();
        if (tid == 0) {
            unsigned rem = misc[4], cum = 0;
            int l = 7;
            for (;; --l) { unsigned v = wsum[l]; if (cum + v >= rem) break; cum += v; }
            int bb = l * 32 + 31;
            for (;; --bb) { unsigned v = hist[bb]; if (cum + v >= rem) break; cum += v; }
            unsigned take = rem - cum;
            unsigned long long pfx2 = (((unsigned long long)misc[3] << 32) | misc[2]) |
                                      ((unsigned long long)bb << (bp * 8));
            misc[2] = (unsigned)pfx2;
            misc[3] = (unsigned)(pfx2 >> 32);
            misc[4] = take;
            if (take == hist[bb]) misc[5] = 1u;
        }
        __syncthreads();
    }
    __syncthreads();
    const unsigned long long T = ((unsigned long long)misc[3] << 32) | misc[2];

    // ======== compact the exactly-K selected keys ========
    for (int j = tid; j < PNUM; j += NT) {
        float s = __ldg(&sp[j]);
        bool sel = false;
        if (s > CONF_THV) {
            unsigned long long key =
                ((unsigned long long)__float_as_uint(s) << 32) |
                (unsigned long long)(0xFFFFFFFFu - (unsigned)j);
            sel = (key >= T);
        }
        unsigned m = __ballot_sync(0xFFFFFFFFu, sel);
        unsigned base = 0;
        if ((tid & 31) == 0 && m) base = atomicAdd(&misc[1], (unsigned)__popc(m));
        base = __shfl_sync(0xFFFFFFFFu, base, 0);
        if (sel) {
            unsigned pos = base + __popc(m & ((1u << (tid & 31)) - 1u));
            sel_s[pos] = s;
            sel_i[pos] = j;
        }
    }
    __syncthreads();
    for (int i = tid; i < 512; i += NT)
        if (i >= K) { sel_s[i] = -1.0f; sel_i[i] = 0x40000000 + i; }
    __syncthreads();

    // ======== bitonic sort 512 (2 elems/thread): desc, ties smaller idx ======
    for (unsigned k = 2; k <= 512; k <<= 1) {
        for (unsigned jj = k >> 1; jj > 0; jj >>= 1) {
#pragma unroll
            for (int half = 0; half < 512; half += NT) {
                unsigned i = (unsigned)(half + tid);
                unsigned ixj = i ^ jj;
                if (ixj > i) {
                    float si = sel_s[i], sx = sel_s[ixj];
                    int ii = sel_i[i], ix = sel_i[ixj];
                    bool g = (sx > si) || (sx == si && ix < ii);
                    bool asc = ((i & k) == 0);
                    if (asc ? g : !g) {
                        sel_s[i] = sx; sel_s[ixj] = si;
                        sel_i[i] = ix; sel_i[ixj] = ii;
                    }
                }
            }
            __syncthreads();
        }
    }

    // ======== gather boxes + precompute c_i = NMS_COEF * area_i ========
    for (int i = tid; i < 512; i += NT) {
        float4 bb = make_float4(0.f, 0.f, 0.f, 0.f);
        float a = 0.f;
        if (i < K) {
            bb = g_boxes[(size_t)b * PNUM + sel_i[i]];
            a = (bb.z - bb.x) * (bb.w - bb.y);
        }
        bx4[i] = bb;
        s_c[i] = NMS_COEF * a;
    }
    __syncthreads();

    // ======== column-strip triangle suppression bitmatrix ========
    // Warp w owns word-columns {w, 15-w}: (w+1)*32 + (16-w)*32 = 544 rows each.
    // Lane = fixed candidate j in the column strip -> bj/cj in registers.
    // sup(i,j) == inter > c_i + c_j  (algebraic form of iou > TH; union > 0)
    {
        const int wid  = tid >> 5;
        const int lane = tid & 31;
#pragma unroll
        for (int pass = 0; pass < 2; ++pass) {
            const int W = pass ? (15 - wid) : wid;
            const int j = (W << 5) + lane;
            const float4 bj = bx4[j];
            const float  cj = s_c[j];
            for (int rb = 0; rb <= W; ++rb) {          // row blocks covered by col W
                unsigned* dst = mat + tri_base(rb) + (W - rb);
                const int nw = 16 - rb;
#pragma unroll 4
                for (int rr = 0; rr < 32; ++rr) {
                    const int r = (rb << 5) + rr;
                    float4 bi = bx4[r];                 // broadcast LDS.128
                    float xx1 = fmaxf(bi.x, bj.x);
                    float yy1 = fmaxf(bi.y, bj.y);
                    float xx2 = fminf(bi.z, bj.z);
                    float yy2 = fminf(bi.w, bj.w);
                    float iw = fmaxf(xx2 - xx1, 0.0f);
                    float ih = fmaxf(yy2 - yy1, 0.0f);
                    float inter = iw * ih;
                    bool sup = inter > (s_c[r] + cj);   // broadcast LDS
                    unsigned bits = __ballot_sync(0xFFFFFFFFu, sup);
                    if (lane == 0) dst[rr * nw] = bits;
                }
            }
        }
    }
    __syncthreads();

    // ======== greedy NMS walk: ONE thread, alive[16] in REGISTERS ========
    if (tid == 0) {
        unsigned alive[16];
#pragma unroll
        for (int ww = 0; ww < 16; ++ww) {
            int n = K - ww * 32;
            alive[ww] = (n >= 32) ? 0xFFFFFFFFu : (n > 0 ? ((1u << n) - 1u) : 0u);
        }
        int cnt = 0;
#pragma unroll
        for (int W = 0; W < 16; ++W) {
            const int nw = 16 - W;
            const unsigned* blk = mat + tri_base(W);
            unsigned cur = alive[W];
            while (cur) {
                int bit = __ffs(cur) - 1;
                pord[cnt++] = (W << 5) + bit;
                const unsigned* mrow = blk + bit * nw;
                cur &= ~mrow[0];                 // self bit clears (iou=1 > TH)
#pragma unroll
                for (int ww = W + 1; ww < 16; ++ww)
                    alive[ww] &= ~mrow[ww - W];
            }
        }
        misc[7] = (unsigned)cnt;
    }
    __syncthreads();

    // ======== writeout ========
    const int cnt = (int)misc[7];
    for (int t = tid; t < TOPK; t += NT) {
        float r0 = 0.f, r1 = 0.f, r2 = 0.f, r3 = 0.f, r4 = 0.f;
        if (t < cnt) {
            int p = pord[t];
            float4 bb = bx4[p];
            r0 = sel_s[p]; r1 = bb.x; r2 = bb.y; r3 = bb.z; r4 = bb.w;
        }
        outp[t * 5 + 0] = r0;
        outp[t * 5 + 1] = r1;
        outp[t * 5 + 2] = r2;
        outp[t * 5 + 3] = r3;
        outp[t * 5 + 4] = r4;
    }
}

extern "C" void kernel_launch(void* const* d_in, const int* in_sizes, int n_in,
                              void* d_out, int out_size) {
    const float* arm_loc  = (const float*)d_in[0];
    const float* arm_conf = (const float*)d_in[1];
    const float* odm_loc  = (const float*)d_in[2];
    const float* odm_conf = (const float*)d_in[3];
    const float* priors   = (const float*)d_in[4];
    float* out = (float*)d_out;

    cudaFuncSetAttribute(task_kernel, cudaFuncAttributeMaxDynamicSharedMemorySize,
                         SMEM_TOTAL);

    int total = BATCH * PNUM;
    prep_kernel<<<(total + 255) / 256, 256>>>(arm_loc, arm_conf, odm_loc, odm_conf,
                                              priors);
    task_kernel<<<BATCH * NCLS, NT, SMEM_TOTAL>>>(out);
}

// round 9
// speedup vs baseline: 1.8074x; 1.1727x over previous
#include <cuda_runtime.h>

#define PNUM 16320
#define BATCH 32
#define NCLS 21
#define TOPK 500
#define CONF_THV 0.01f
#define NMS_THV 0.45f
#define OBJ_THV 0.01f
#define NT 256
// TH/(1+TH) for the transformed suppression test
#define NMS_COEF 0.310344827586206896f
#define NQ4 4080   // PNUM/4 float4 loads

// ---- device scratch (no allocations allowed) ----
__device__ float4 g_boxes[BATCH * PNUM];                 // decoded boxes (x1,y1,x2,y2)
__device__ float  g_scores[BATCH * (NCLS - 1) * PNUM];   // arm-masked scores, [B][20][P]

// ---- shared memory layout (bytes) ----
#define OFF_MISC   0        // 64 (16 u32)
#define OFF_SELS   64       // 512*4 = 2048
#define OFF_SELI   2112     // 2048
#define OFF_BOX    4160     // 512*16 = 8192 (16B aligned)
#define OFF_AREA   12352    // 2048  (holds c_i = NMS_COEF * area_i)
#define OFF_PORD   14400    // 2048
#define OFF_MAT    16448    // triangle-packed 4352 words = 17408
#define SMEM_TOTAL 33856    // single wave at ~4.5 blocks/SM
// overlays inside MAT (dead until matrix phase)
#define OFF_HIST   16448    // 2048*4 = 8192
#define OFF_PART   24640    // 256*4
#define OFF_WSUM   25664    // 8*4
#define OFF_EQ     25696    // 512*4

// misc: 1=ncomp 2=THR 3=ntie 4=rem/take 5=done 6=K 7=cnt 8=prefix 9=neq 13=tieTake

// triangle packing: rows grouped by block rb=r>>5; row r stores words rb..15
__host__ __device__ __forceinline__ int tri_base(int rb) {
    return 512 * rb - 16 * rb * (rb - 1);
}

// =====================================================================
// Kernel 1: cascaded decode + arm-masked score transpose
// =====================================================================
__global__ void prep_kernel(const float* __restrict__ arm_loc,
                            const float* __restrict__ arm_conf,
                            const float* __restrict__ odm_loc,
                            const float* __restrict__ odm_conf,
                            const float* __restrict__ priors) {
    int idx = blockIdx.x * blockDim.x + threadIdx.x;
    if (idx >= BATCH * PNUM) return;
    int b = idx / PNUM;
    int p = idx % PNUM;

    float pcx = priors[p * 4 + 0];
    float pcy = priors[p * 4 + 1];
    float pw  = priors[p * 4 + 2];
    float ph  = priors[p * 4 + 3];

    const float* al = arm_loc + (size_t)idx * 4;
    const float* ol = odm_loc + (size_t)idx * 4;

    float cx = pcx + al[0] * 0.1f * pw;
    float cy = pcy + al[1] * 0.1f * ph;
    float w  = pw * expf(al[2] * 0.2f);
    float h  = ph * expf(al[3] * 0.2f);
    float mnx = cx - w * 0.5f;
    float mny = cy - h * 0.5f;
    float mxx = mnx + w;
    float mxy = mny + h;
    float dcx = (mxx + mnx) * 0.5f;
    float dcy = (mxy + mny) * 0.5f;
    float dw  = mxx - mnx;
    float dh  = mxy - mny;

    float cx2 = dcx + ol[0] * 0.1f * dw;
    float cy2 = dcy + ol[1] * 0.1f * dh;
    float w2  = dw * expf(ol[2] * 0.2f);
    float h2  = dh * expf(ol[3] * 0.2f);
    float x1 = cx2 - w2 * 0.5f;
    float y1 = cy2 - h2 * 0.5f;
    float x2 = x1 + w2;
    float y2 = y1 + h2;
    g_boxes[idx] = make_float4(x1, y1, x2, y2);

    bool armpass = arm_conf[(size_t)idx * 2 + 1] > OBJ_THV;
    const float* oc = odm_conf + (size_t)idx * NCLS;
#pragma unroll
    for (int c = 1; c < NCLS; ++c) {
        float v = armpass ? oc[c] : 0.0f;
        g_scores[((size_t)(b * (NCLS - 1) + (c - 1))) * PNUM + p] = v;
    }
}

// =====================================================================
// Kernel 2: per (image,class), 256 threads. 32-bit 11/11/10-digit radix
// select (exact lax.top_k ties via eq-list), bitonic sort, merged
// column-strip triangle suppression matrix, register-resident NMS walk
// overlapped with output zero-fill.
// =====================================================================
__global__ void __launch_bounds__(NT) task_kernel(float* __restrict__ out) {
    extern __shared__ __align__(16) char smraw[];
    unsigned* misc   = (unsigned*)(smraw + OFF_MISC);
    float*    sel_s  = (float*)(smraw + OFF_SELS);
    int*      sel_i  = (int*)(smraw + OFF_SELI);
    float4*   bx4    = (float4*)(smraw + OFF_BOX);
    float*    s_c    = (float*)(smraw + OFF_AREA);
    int*      pord   = (int*)(smraw + OFF_PORD);
    unsigned* mat    = (unsigned*)(smraw + OFF_MAT);
    unsigned* hist   = (unsigned*)(smraw + OFF_HIST);
    unsigned* part   = (unsigned*)(smraw + OFF_PART);
    unsigned* wsum   = (unsigned*)(smraw + OFF_WSUM);
    unsigned* eq     = (unsigned*)(smraw + OFF_EQ);

    const int tid = threadIdx.x;
    const int b   = blockIdx.x / NCLS;
    const int cl  = blockIdx.x % NCLS;
    float* outp = out + (size_t)(b * NCLS + cl) * (TOPK * 5);

    if (cl == 0) {  // background class: all zeros
        for (int e = tid; e < TOPK * 5; e += NT) outp[e] = 0.0f;
        return;
    }

    const float* __restrict__ sp =
        g_scores + (size_t)(b * (NCLS - 1) + (cl - 1)) * PNUM;
    const float4* __restrict__ sp4 = (const float4*)sp;

    // ======== PASS A: 2048-bin histogram on kb>>21 (match-aggregated) ========
    for (int h = tid; h < 2048; h += NT) hist[h] = 0u;
    if (tid < 16) misc[tid] = 0u;
    __syncthreads();

#pragma unroll 1
    for (int it = 0; it < 16; ++it) {          // uniform trip count
        int j4 = it * NT + tid;
        float4 sv = make_float4(0.f, 0.f, 0.f, 0.f);
        bool inb = j4 < NQ4;
        if (inb) sv = sp4[j4];
#pragma unroll
        for (int e = 0; e < 4; ++e) {
            float s = (e == 0) ? sv.x : (e == 1) ? sv.y : (e == 2) ? sv.z : sv.w;
            int bin = (inb && s > CONF_THV) ? (int)(__float_as_uint(s) >> 21) : -1;
            unsigned grp = __match_any_sync(0xFFFFFFFFu, bin);
            if (((unsigned)tid & 31u) == (unsigned)(__ffs(grp) - 1) && bin >= 0)
                atomicAdd(&hist[bin], (unsigned)__popc(grp));
        }
    }
    __syncthreads();
    {   // reduce 2048 bins: 8/thread -> part[256] -> wsum[8]
        unsigned v = 0;
#pragma unroll
        for (int q = 0; q < 8; ++q) v += hist[tid * 8 + q];
        part[tid] = v;
#pragma unroll
        for (int o = 16; o; o >>= 1) v += __shfl_down_sync(0xFFFFFFFFu, v, o);
        if ((tid & 31) == 0) wsum[tid >> 5] = v;
    }
    __syncthreads();
    if (tid == 0) {
        unsigned total = 0;
        for (int l = 0; l < 8; ++l) total += wsum[l];
        unsigned K = total < TOPK ? total : TOPK;
        misc[6] = K;
        if (K > 0) {
            unsigned rem = K, cum = 0;
            int l = 7;
            for (;; --l) { unsigned v = wsum[l]; if (cum + v >= rem) break; cum += v; }
            int p = l * 32 + 31;
            for (;; --p) { unsigned v = part[p]; if (cum + v >= rem) break; cum += v; }
            int bb = p * 8 + 7;
            for (;; --bb) { unsigned v = hist[bb]; if (cum + v >= rem) break; cum += v; }
            unsigned take = rem - cum;
            misc[8] = (unsigned)bb;
            misc[4] = take;
            if (take == hist[bb]) {       // whole 11-bit bin selected
                misc[2] = (unsigned)bb << 21;
                misc[3] = 0u;
                misc[5] = 1u;
            }
        }
    }
    __syncthreads();

    const int K = (int)misc[6];
    if (K == 0) {
        for (int e = tid; e < TOPK * 5; e += NT) outp[e] = 0.0f;
        return;
    }

    // ======== PASS B: bits 10..20 within bin bselA (plain atomics) ========
    if (!misc[5]) {
        const unsigned bselA = misc[8];
        for (int h = tid; h < 2048; h += NT) hist[h] = 0u;
        __syncthreads();
        for (int j4 = tid; j4 < NQ4; j4 += NT) {   // no collectives: divergence OK
            float4 sv = sp4[j4];
#pragma unroll
            for (int e = 0; e < 4; ++e) {
                float s = (e == 0) ? sv.x : (e == 1) ? sv.y : (e == 2) ? sv.z : sv.w;
                unsigned kb = __float_as_uint(s);
                if (s > CONF_THV && (kb >> 21) == bselA)
                    atomicAdd(&hist[(kb >> 10) & 0x7FFu], 1u);
            }
        }
        __syncthreads();
        {
            unsigned v = 0;
#pragma unroll
            for (int q = 0; q < 8; ++q) v += hist[tid * 8 + q];
            part[tid] = v;
#pragma unroll
            for (int o = 16; o; o >>= 1) v += __shfl_down_sync(0xFFFFFFFFu, v, o);
            if ((tid & 31) == 0) wsum[tid >> 5] = v;
        }
        __syncthreads();
        if (tid == 0) {
            unsigned rem = misc[4], cum = 0;
            int l = 7;
            for (;; --l) { unsigned v = wsum[l]; if (cum + v >= rem) break; cum += v; }
            int p = l * 32 + 31;
            for (;; --p) { unsigned v = part[p]; if (cum + v >= rem) break; cum += v; }
            int bb = p * 8 + 7;
            for (;; --bb) { unsigned v = hist[bb]; if (cum + v >= rem) break; cum += v; }
            unsigned take = rem - cum;
            unsigned pfx2 = (bselA << 11) | (unsigned)bb;
            misc[8] = pfx2;
            misc[4] = take;
            if (take == hist[bb]) {
                misc[2] = pfx2 << 10;
                misc[3] = 0u;
                misc[5] = 1u;
            }
        }
        __syncthreads();
    }

    // ======== PASS C (rare): bits 0..9 within 22-bit prefix ========
    if (!misc[5]) {
        const unsigned pfx2 = misc[8];
        for (int h = tid; h < 1024; h += NT) hist[h] = 0u;
        __syncthreads();
        for (int j4 = tid; j4 < NQ4; j4 += NT) {
            float4 sv = sp4[j4];
#pragma unroll
            for (int e = 0; e < 4; ++e) {
                float s = (e == 0) ? sv.x : (e == 1) ? sv.y : (e == 2) ? sv.z : sv.w;
                unsigned kb = __float_as_uint(s);
                if (s > CONF_THV && (kb >> 10) == pfx2)
                    atomicAdd(&hist[kb & 0x3FFu], 1u);
            }
        }
        __syncthreads();
        {
            unsigned v = 0;
#pragma unroll
            for (int q = 0; q < 4; ++q) v += hist[tid * 4 + q];
            part[tid] = v;
#pragma unroll
            for (int o = 16; o; o >>= 1) v += __shfl_down_sync(0xFFFFFFFFu, v, o);
            if ((tid & 31) == 0) wsum[tid >> 5] = v;
        }
        __syncthreads();
        if (tid == 0) {
            unsigned rem = misc[4], cum = 0;
            int l = 7;
            for (;; --l) { unsigned v = wsum[l]; if (cum + v >= rem) break; cum += v; }
            int p = l * 32 + 31;
            for (;; --p) { unsigned v = part[p]; if (cum + v >= rem) break; cum += v; }
            int bb = p * 4 + 3;
            for (;; --bb) { unsigned v = hist[bb]; if (cum + v >= rem) break; cum += v; }
            unsigned take = rem - cum;
            misc[2] = (pfx2 << 10) | (unsigned)bb;     // exact 32-bit score
            if (take == hist[bb]) {
                misc[3] = 0u;
            } else {
                misc[3] = 1u;                          // tie among identical scores
                misc[13] = take;
            }
        }
        __syncthreads();
    }

    // ======== final compaction scan ========
    const unsigned THR  = misc[2];
    const unsigned ntie = misc[3];
#pragma unroll 1
    for (int it = 0; it < 16; ++it) {                  // uniform trips (ballot)
        int j4 = it * NT + tid;
        float4 sv = make_float4(0.f, 0.f, 0.f, 0.f);
        bool inb = j4 < NQ4;
        if (inb) sv = sp4[j4];
#pragma unroll
        for (int e = 0; e < 4; ++e) {
            float s = (e == 0) ? sv.x : (e == 1) ? sv.y : (e == 2) ? sv.z : sv.w;
            unsigned kb = __float_as_uint(s);
            bool cand = inb && (s > CONF_THV);
            bool sel = cand && (ntie ? (kb > THR) : (kb >= THR));
            unsigned m = __ballot_sync(0xFFFFFFFFu, sel);
            unsigned base = 0;
            if ((tid & 31) == 0 && m) base = atomicAdd(&misc[1], (unsigned)__popc(m));
            base = __shfl_sync(0xFFFFFFFFu, base, 0);
            if (sel) {
                unsigned pos = base + __popc(m & ((1u << (tid & 31)) - 1u));
                sel_s[pos] = s;
                sel_i[pos] = j4 * 4 + e;
            }
            if (ntie && cand && kb == THR) {
                unsigned p = atomicAdd(&misc[9], 1u);
                if (p < 512) eq[p] = (unsigned)(j4 * 4 + e);
            }
        }
    }
    __syncthreads();
    if (ntie && tid == 0) {    // take smallest indices among exact-score ties
        int neq = (int)misc[9]; if (neq > 512) neq = 512;
        int take = (int)misc[13]; if (take > neq) take = neq;
        int base = (int)misc[1];
        for (int t = 0; t < take; ++t) {
            unsigned best = 0xFFFFFFFFu; int bi = 0;
            for (int q = 0; q < neq; ++q)
                if (eq[q] < best) { best = eq[q]; bi = q; }
            eq[bi] = 0xFFFFFFFFu;
            sel_s[base + t] = __uint_as_float(THR);
            sel_i[base + t] = (int)best;
        }
        misc[1] = (unsigned)(base + take);
    }
    __syncthreads();
    for (int i = tid; i < 512; i += NT)
        if (i >= K) { sel_s[i] = -1.0f; sel_i[i] = 0x40000000 + i; }
    __syncthreads();

    // ======== bitonic sort 512 (2 elems/thread): desc, ties smaller idx ======
    for (unsigned k = 2; k <= 512; k <<= 1) {
        for (unsigned jj = k >> 1; jj > 0; jj >>= 1) {
#pragma unroll
            for (int half = 0; half < 512; half += NT) {
                unsigned i = (unsigned)(half + tid);
                unsigned ixj = i ^ jj;
                if (ixj > i) {
                    float si = sel_s[i], sx = sel_s[ixj];
                    int ii = sel_i[i], ix = sel_i[ixj];
                    bool g = (sx > si) || (sx == si && ix < ii);
                    bool asc = ((i & k) == 0);
                    if (asc ? g : !g) {
                        sel_s[i] = sx; sel_s[ixj] = si;
                        sel_i[i] = ix; sel_i[ixj] = ii;
                    }
                }
            }
            __syncthreads();
        }
    }

    // ======== gather boxes + precompute c_i = NMS_COEF * area_i ========
    for (int i = tid; i < 512; i += NT) {
        float4 bb = make_float4(0.f, 0.f, 0.f, 0.f);
        float a = 0.f;
        if (i < K) {
            bb = g_boxes[(size_t)b * PNUM + sel_i[i]];
            a = (bb.z - bb.x) * (bb.w - bb.y);
        }
        bx4[i] = bb;
        s_c[i] = NMS_COEF * a;
    }
    __syncthreads();

    // ======== merged column-strip triangle suppression bitmatrix ========
    // Warp w owns word-columns W1=w and W2=15-w, sharing bi/c_i loads.
    // sup(i,j) == inter > c_i + c_j  (algebraic iou > TH; union > 0)
    {
        const int w    = tid >> 5;
        const int lane = tid & 31;
        const int W2   = 15 - w;
        const int j1   = (w  << 5) + lane;
        const int j2   = (W2 << 5) + lane;
        const float4 bj1 = bx4[j1];
        const float  cj1 = s_c[j1];
        const float4 bj2 = bx4[j2];
        const float  cj2 = s_c[j2];
        for (int rb = 0; rb <= W2; ++rb) {
            const int nw = 16 - rb;
            unsigned* base1 = mat + tri_base(rb) + (w  - rb);
            unsigned* base2 = mat + tri_base(rb) + (W2 - rb);
            const bool do1 = (rb <= w);                 // warp-uniform
#pragma unroll 4
            for (int rr = 0; rr < 32; ++rr) {
                const int r = (rb << 5) + rr;
                const float4 bi = bx4[r];               // broadcast LDS.128
                const float  ci = s_c[r];
                {
                    float xx1 = fmaxf(bi.x, bj2.x);
                    float yy1 = fmaxf(bi.y, bj2.y);
                    float xx2 = fminf(bi.z, bj2.z);
                    float yy2 = fminf(bi.w, bj2.w);
                    float iw = fmaxf(xx2 - xx1, 0.0f);
                    float ih = fmaxf(yy2 - yy1, 0.0f);
                    bool sup = (iw * ih) > (ci + cj2);
                    unsigned bits = __ballot_sync(0xFFFFFFFFu, sup);
                    if (lane == 0) base2[rr * nw] = bits;
                }
                if (do1) {
                    float xx1 = fmaxf(bi.x, bj1.x);
                    float yy1 = fmaxf(bi.y, bj1.y);
                    float xx2 = fminf(bi.z, bj1.z);
                    float yy2 = fminf(bi.w, bj1.w);
                    float iw = fmaxf(xx2 - xx1, 0.0f);
                    float ih = fmaxf(yy2 - yy1, 0.0f);
                    bool sup = (iw * ih) > (ci + cj1);
                    unsigned bits = __ballot_sync(0xFFFFFFFFu, sup);
                    if (lane == 0) base1[rr * nw] = bits;
                }
            }
        }
    }
    __syncthreads();

    // ======== NMS walk on thread 0 (alive in regs), overlapped with
    //          output zero-fill by warps 1..7 ========
    if (tid == 0) {
        unsigned alive[16];
#pragma unroll
        for (int ww = 0; ww < 16; ++ww) {
            int n = K - ww * 32;
            alive[ww] = (n >= 32) ? 0xFFFFFFFFu : (n > 0 ? ((1u << n) - 1u) : 0u);
        }
        int cnt = 0;
#pragma unroll
        for (int W = 0; W < 16; ++W) {
            const int nw = 16 - W;
            const unsigned* blk = mat + tri_base(W);
            unsigned cur = alive[W];
            while (cur) {
                int bit = __ffs(cur) - 1;
                pord[cnt++] = (W << 5) + bit;
                const unsigned* mrow = blk + bit * nw;
                cur &= ~mrow[0];                 // self bit clears (iou=1 > TH)
#pragma unroll
                for (int ww = W + 1; ww < 16; ++ww)
                    alive[ww] &= ~mrow[ww - W];
            }
        }
        misc[7] = (unsigned)cnt;
    } else if (tid >= 32) {
        for (int e = tid - 32; e < TOPK * 5; e += NT - 32) outp[e] = 0.0f;
    }
    __syncthreads();

    // ======== writeout (live rows only; rest already zero) ========
    const int cnt = (int)misc[7];
    for (int t = tid; t < cnt; t += NT) {
        int p = pord[t];
        float4 bb = bx4[p];
        outp[t * 5 + 0] = sel_s[p];
        outp[t * 5 + 1] = bb.x;
        outp[t * 5 + 2] = bb.y;
        outp[t * 5 + 3] = bb.z;
        outp[t * 5 + 4] = bb.w;
    }
}

extern "C" void kernel_launch(void* const* d_in, const int* in_sizes, int n_in,
                              void* d_out, int out_size) {
    const float* arm_loc  = (const float*)d_in[0];
    const float* arm_conf = (const float*)d_in[1];
    const float* odm_loc  = (const float*)d_in[2];
    const float* odm_conf = (const float*)d_in[3];
    const float* priors   = (const float*)d_in[4];
    float* out = (float*)d_out;

    cudaFuncSetAttribute(task_kernel, cudaFuncAttributeMaxDynamicSharedMemorySize,
                         SMEM_TOTAL);

    int total = BATCH * PNUM;
    prep_kernel<<<(total + 255) / 256, 256>>>(arm_loc, arm_conf, odm_loc, odm_conf,
                                              priors);
    task_kernel<<<BATCH * NCLS, NT, SMEM_TOTAL>>>(out);
}

// round 11
// speedup vs baseline: 1.8922x; 1.0469x over previous
#include <cuda_runtime.h>

#define PNUM 16320
#define BATCH 32
#define NCLS 21
#define TOPK 500
#define CONF_THV 0.01f
#define NMS_THV 0.45f
#define OBJ_THV 0.01f
#define NT 256
// TH/(1+TH) for the transformed suppression test
#define NMS_COEF 0.310344827586206896f
#define NQ4 4080   // PNUM/4 float4 loads

// ---- device scratch (no allocations allowed) ----
__device__ float4 g_boxes[BATCH * PNUM];                 // decoded boxes (x1,y1,x2,y2)
__device__ float  g_scores[BATCH * (NCLS - 1) * PNUM];   // arm-masked scores, [B][20][P]

// ---- shared memory layout (bytes) ----
#define OFF_MISC   0        // 64 (16 u32)
#define OFF_SELS   64       // 512*4 = 2048
#define OFF_SELI   2112     // 2048
#define OFF_BOX    4160     // 512*16 = 8192 (16B aligned)
#define OFF_AREA   12352    // 2048  (holds c_i = NMS_COEF * area_i)
#define OFF_PORD   14400    // 2048
#define OFF_MAT    16448    // triangle-packed 4352 words = 17408
#define SMEM_TOTAL 33856    // single wave
// overlays inside MAT (dead until matrix phase)
#define OFF_HIST   16448    // 2048*4 = 8192
#define OFF_PART   24640    // 256*4
#define OFF_WSUM   25664    // 8*4
#define OFF_EQ     25696    // 512*4

// misc: 1=ncomp 2=THR 3=ntie 4=rem/take 5=done 6=K 7=cnt 8=prefix 9=neq 13=tieTake

// triangle packing: rows grouped by block rb=r>>5; row r stores words rb..15
__host__ __device__ __forceinline__ int tri_base(int rb) {
    return 512 * rb - 16 * rb * (rb - 1);
}

// 72 equal 32x32 tiles (p=column pair, rb=row block; rb <= 2p+1), 9 per warp
__device__ __constant__ unsigned char TP[72] = {
    0,0, 1,1,1,1, 2,2,2,2,2,2, 3,3,3,3,3,3,3,3,
    4,4,4,4,4,4,4,4,4,4, 5,5,5,5,5,5,5,5,5,5,5,5,
    6,6,6,6,6,6,6,6,6,6,6,6,6,6, 7,7,7,7,7,7,7,7,7,7,7,7,7,7,7,7};
__device__ __constant__ unsigned char TRB[72] = {
    0,1, 0,1,2,3, 0,1,2,3,4,5, 0,1,2,3,4,5,6,7,
    0,1,2,3,4,5,6,7,8,9, 0,1,2,3,4,5,6,7,8,9,10,11,
    0,1,2,3,4,5,6,7,8,9,10,11,12,13, 0,1,2,3,4,5,6,7,8,9,10,11,12,13,14,15};

// =====================================================================
// Kernel 1: cascaded decode + arm-masked score transpose
// =====================================================================
__global__ void prep_kernel(const float* __restrict__ arm_loc,
                            const float* __restrict__ arm_conf,
                            const float* __restrict__ odm_loc,
                            const float* __restrict__ odm_conf,
                            const float* __restrict__ priors) {
    int idx = blockIdx.x * blockDim.x + threadIdx.x;
    if (idx >= BATCH * PNUM) return;
    int b = idx / PNUM;
    int p = idx % PNUM;

    float pcx = priors[p * 4 + 0];
    float pcy = priors[p * 4 + 1];
    float pw  = priors[p * 4 + 2];
    float ph  = priors[p * 4 + 3];

    const float* al = arm_loc + (size_t)idx * 4;
    const float* ol = odm_loc + (size_t)idx * 4;

    float cx = pcx + al[0] * 0.1f * pw;
    float cy = pcy + al[1] * 0.1f * ph;
    float w  = pw * expf(al[2] * 0.2f);
    float h  = ph * expf(al[3] * 0.2f);
    float mnx = cx - w * 0.5f;
    float mny = cy - h * 0.5f;
    float mxx = mnx + w;
    float mxy = mny + h;
    float dcx = (mxx + mnx) * 0.5f;
    float dcy = (mxy + mny) * 0.5f;
    float dw  = mxx - mnx;
    float dh  = mxy - mny;

    float cx2 = dcx + ol[0] * 0.1f * dw;
    float cy2 = dcy + ol[1] * 0.1f * dh;
    float w2  = dw * expf(ol[2] * 0.2f);
    float h2  = dh * expf(ol[3] * 0.2f);
    float x1 = cx2 - w2 * 0.5f;
    float y1 = cy2 - h2 * 0.5f;
    float x2 = x1 + w2;
    float y2 = y1 + h2;
    g_boxes[idx] = make_float4(x1, y1, x2, y2);

    bool armpass = arm_conf[(size_t)idx * 2 + 1] > OBJ_THV;
    const float* oc = odm_conf + (size_t)idx * NCLS;
#pragma unroll
    for (int c = 1; c < NCLS; ++c) {
        float v = armpass ? oc[c] : 0.0f;
        g_scores[((size_t)(b * (NCLS - 1) + (c - 1))) * PNUM + p] = v;
    }
}

// =====================================================================
// Kernel 2: per (image,class), 256 threads. 32-bit 11/11/10-digit radix
// select, bitonic sort, adjacent-pair LUT-balanced suppression matrix
// (shared row loads, fma-form test), register-resident NMS walk.
// =====================================================================
__global__ void __launch_bounds__(NT) task_kernel(float* __restrict__ out) {
    extern __shared__ __align__(16) char smraw[];
    unsigned* misc   = (unsigned*)(smraw + OFF_MISC);
    float*    sel_s  = (float*)(smraw + OFF_SELS);
    int*      sel_i  = (int*)(smraw + OFF_SELI);
    float4*   bx4    = (float4*)(smraw + OFF_BOX);
    float*    s_c    = (float*)(smraw + OFF_AREA);
    int*      pord   = (int*)(smraw + OFF_PORD);
    unsigned* mat    = (unsigned*)(smraw + OFF_MAT);
    unsigned* hist   = (unsigned*)(smraw + OFF_HIST);
    unsigned* part   = (unsigned*)(smraw + OFF_PART);
    unsigned* wsum   = (unsigned*)(smraw + OFF_WSUM);
    unsigned* eq     = (unsigned*)(smraw + OFF_EQ);

    const int tid = threadIdx.x;
    const int b   = blockIdx.x / NCLS;
    const int cl  = blockIdx.x % NCLS;
    float* outp = out + (size_t)(b * NCLS + cl) * (TOPK * 5);

    if (cl == 0) {  // background class: all zeros
        for (int e = tid; e < TOPK * 5; e += NT) outp[e] = 0.0f;
        return;
    }

    const float* __restrict__ sp =
        g_scores + (size_t)(b * (NCLS - 1) + (cl - 1)) * PNUM;
    const float4* __restrict__ sp4 = (const float4*)sp;

    // ======== PASS A: 2048-bin histogram on kb>>21 (match-aggregated) ========
    for (int h = tid; h < 2048; h += NT) hist[h] = 0u;
    if (tid < 16) misc[tid] = 0u;
    __syncthreads();

#pragma unroll 1
    for (int it = 0; it < 16; ++it) {          // uniform trip count
        int j4 = it * NT + tid;
        float4 sv = make_float4(0.f, 0.f, 0.f, 0.f);
        bool inb = j4 < NQ4;
        if (inb) sv = sp4[j4];
#pragma unroll
        for (int e = 0; e < 4; ++e) {
            float s = (e == 0) ? sv.x : (e == 1) ? sv.y : (e == 2) ? sv.z : sv.w;
            int bin = (inb && s > CONF_THV) ? (int)(__float_as_uint(s) >> 21) : -1;
            unsigned grp = __match_any_sync(0xFFFFFFFFu, bin);
            if (((unsigned)tid & 31u) == (unsigned)(__ffs(grp) - 1) && bin >= 0)
                atomicAdd(&hist[bin], (unsigned)__popc(grp));
        }
    }
    __syncthreads();
    {   // reduce 2048 bins: 8/thread -> part[256] -> wsum[8]
        unsigned v = 0;
#pragma unroll
        for (int q = 0; q < 8; ++q) v += hist[tid * 8 + q];
        part[tid] = v;
#pragma unroll
        for (int o = 16; o; o >>= 1) v += __shfl_down_sync(0xFFFFFFFFu, v, o);
        if ((tid & 31) == 0) wsum[tid >> 5] = v;
    }
    __syncthreads();
    if (tid == 0) {
        unsigned total = 0;
        for (int l = 0; l < 8; ++l) total += wsum[l];
        unsigned K = total < TOPK ? total : TOPK;
        misc[6] = K;
        if (K > 0) {
            unsigned rem = K, cum = 0;
            int l = 7;
            for (;; --l) { unsigned v = wsum[l]; if (cum + v >= rem) break; cum += v; }
            int p = l * 32 + 31;
            for (;; --p) { unsigned v = part[p]; if (cum + v >= rem) break; cum += v; }
            int bb = p * 8 + 7;
            for (;; --bb) { unsigned v = hist[bb]; if (cum + v >= rem) break; cum += v; }
            unsigned take = rem - cum;
            misc[8] = (unsigned)bb;
            misc[4] = take;
            if (take == hist[bb]) {       // whole 11-bit bin selected
                misc[2] = (unsigned)bb << 21;
                misc[3] = 0u;
                misc[5] = 1u;
            }
        }
    }
    __syncthreads();

    const int K = (int)misc[6];
    if (K == 0) {
        for (int e = tid; e < TOPK * 5; e += NT) outp[e] = 0.0f;
        return;
    }

    // ======== PASS B: bits 10..20 within bin bselA (plain atomics) ========
    if (!misc[5]) {
        const unsigned bselA = misc[8];
        for (int h = tid; h < 2048; h += NT) hist[h] = 0u;
        __syncthreads();
        for (int j4 = tid; j4 < NQ4; j4 += NT) {   // no collectives: divergence OK
            float4 sv = sp4[j4];
#pragma unroll
            for (int e = 0; e < 4; ++e) {
                float s = (e == 0) ? sv.x : (e == 1) ? sv.y : (e == 2) ? sv.z : sv.w;
                unsigned kb = __float_as_uint(s);
                if (s > CONF_THV && (kb >> 21) == bselA)
                    atomicAdd(&hist[(kb >> 10) & 0x7FFu], 1u);
            }
        }
        __syncthreads();
        {
            unsigned v = 0;
#pragma unroll
            for (int q = 0; q < 8; ++q) v += hist[tid * 8 + q];
            part[tid] = v;
#pragma unroll
            for (int o = 16; o; o >>= 1) v += __shfl_down_sync(0xFFFFFFFFu, v, o);
            if ((tid & 31) == 0) wsum[tid >> 5] = v;
        }
        __syncthreads();
        if (tid == 0) {
            unsigned rem = misc[4], cum = 0;
            int l = 7;
            for (;; --l) { unsigned v = wsum[l]; if (cum + v >= rem) break; cum += v; }
            int p = l * 32 + 31;
            for (;; --p) { unsigned v = part[p]; if (cum + v >= rem) break; cum += v; }
            int bb = p * 8 + 7;
            for (;; --bb) { unsigned v = hist[bb]; if (cum + v >= rem) break; cum += v; }
            unsigned take = rem - cum;
            unsigned pfx2 = (bselA << 11) | (unsigned)bb;
            misc[8] = pfx2;
            misc[4] = take;
            if (take == hist[bb]) {
                misc[2] = pfx2 << 10;
                misc[3] = 0u;
                misc[5] = 1u;
            }
        }
        __syncthreads();
    }

    // ======== PASS C (rare): bits 0..9 within 22-bit prefix ========
    if (!misc[5]) {
        const unsigned pfx2 = misc[8];
        for (int h = tid; h < 1024; h += NT) hist[h] = 0u;
        __syncthreads();
        for (int j4 = tid; j4 < NQ4; j4 += NT) {
            float4 sv = sp4[j4];
#pragma unroll
            for (int e = 0; e < 4; ++e) {
                float s = (e == 0) ? sv.x : (e == 1) ? sv.y : (e == 2) ? sv.z : sv.w;
                unsigned kb = __float_as_uint(s);
                if (s > CONF_THV && (kb >> 10) == pfx2)
                    atomicAdd(&hist[kb & 0x3FFu], 1u);
            }
        }
        __syncthreads();
        {
            unsigned v = 0;
#pragma unroll
            for (int q = 0; q < 4; ++q) v += hist[tid * 4 + q];
            part[tid] = v;
#pragma unroll
            for (int o = 16; o; o >>= 1) v += __shfl_down_sync(0xFFFFFFFFu, v, o);
            if ((tid & 31) == 0) wsum[tid >> 5] = v;
        }
        __syncthreads();
        if (tid == 0) {
            unsigned rem = misc[4], cum = 0;
            int l = 7;
            for (;; --l) { unsigned v = wsum[l]; if (cum + v >= rem) break; cum += v; }
            int p = l * 32 + 31;
            for (;; --p) { unsigned v = part[p]; if (cum + v >= rem) break; cum += v; }
            int bb = p * 4 + 3;
            for (;; --bb) { unsigned v = hist[bb]; if (cum + v >= rem) break; cum += v; }
            unsigned take = rem - cum;
            misc[2] = (pfx2 << 10) | (unsigned)bb;     // exact 32-bit score
            if (take == hist[bb]) {
                misc[3] = 0u;
            } else {
                misc[3] = 1u;                          // tie among identical scores
                misc[13] = take;
            }
        }
        __syncthreads();
    }

    // ======== final compaction scan ========
    const unsigned THR  = misc[2];
    const unsigned ntie = misc[3];
#pragma unroll 1
    for (int it = 0; it < 16; ++it) {                  // uniform trips (ballot)
        int j4 = it * NT + tid;
        float4 sv = make_float4(0.f, 0.f, 0.f, 0.f);
        bool inb = j4 < NQ4;
        if (inb) sv = sp4[j4];
#pragma unroll
        for (int e = 0; e < 4; ++e) {
            float s = (e == 0) ? sv.x : (e == 1) ? sv.y : (e == 2) ? sv.z : sv.w;
            unsigned kb = __float_as_uint(s);
            bool cand = inb && (s > CONF_THV);
            bool sel = cand && (ntie ? (kb > THR) : (kb >= THR));
            unsigned m = __ballot_sync(0xFFFFFFFFu, sel);
            unsigned base = 0;
            if ((tid & 31) == 0 && m) base = atomicAdd(&misc[1], (unsigned)__popc(m));
            base = __shfl_sync(0xFFFFFFFFu, base, 0);
            if (sel) {
                unsigned pos = base + __popc(m & ((1u << (tid & 31)) - 1u));
                sel_s[pos] = s;
                sel_i[pos] = j4 * 4 + e;
            }
            if (ntie && cand && kb == THR) {
                unsigned p = atomicAdd(&misc[9], 1u);
                if (p < 512) eq[p] = (unsigned)(j4 * 4 + e);
            }
        }
    }
    __syncthreads();
    if (ntie && tid == 0) {    // take smallest indices among exact-score ties
        int neq = (int)misc[9]; if (neq > 512) neq = 512;
        int take = (int)misc[13]; if (take > neq) take = neq;
        int base = (int)misc[1];
        for (int t = 0; t < take; ++t) {
            unsigned best = 0xFFFFFFFFu; int bi = 0;
            for (int q = 0; q < neq; ++q)
                if (eq[q] < best) { best = eq[q]; bi = q; }
            eq[bi] = 0xFFFFFFFFu;
            sel_s[base + t] = __uint_as_float(THR);
            sel_i[base + t] = (int)best;
        }
        misc[1] = (unsigned)(base + take);
    }
    __syncthreads();
    for (int i = tid; i < 512; i += NT)
        if (i >= K) { sel_s[i] = -1.0f; sel_i[i] = 0x40000000 + i; }
    __syncthreads();

    // ======== bitonic sort 512 (2 elems/thread): desc, ties smaller idx ======
    for (unsigned k = 2; k <= 512; k <<= 1) {
        for (unsigned jj = k >> 1; jj > 0; jj >>= 1) {
#pragma unroll
            for (int half = 0; half < 512; half += NT) {
                unsigned i = (unsigned)(half + tid);
                unsigned ixj = i ^ jj;
                if (ixj > i) {
                    float si = sel_s[i], sx = sel_s[ixj];
                    int ii = sel_i[i], ix = sel_i[ixj];
                    bool g = (sx > si) || (sx == si && ix < ii);
                    bool asc = ((i & k) == 0);
                    if (asc ? g : !g) {
                        sel_s[i] = sx; sel_s[ixj] = si;
                        sel_i[i] = ix; sel_i[ixj] = ii;
                    }
                }
            }
            __syncthreads();
        }
    }

    // ======== gather boxes + precompute c_i = NMS_COEF * area_i ========
    for (int i = tid; i < 512; i += NT) {
        float4 bb = make_float4(0.f, 0.f, 0.f, 0.f);
        float a = 0.f;
        if (i < K) {
            bb = g_boxes[(size_t)b * PNUM + sel_i[i]];
            a = (bb.z - bb.x) * (bb.w - bb.y);
        }
        bx4[i] = bb;
        s_c[i] = NMS_COEF * a;
    }
    __syncthreads();

    // ======== suppression matrix over 72 balanced adjacent-pair tiles ========
    // Tile (p, rb): columns W1=2p, W2=2p+1; rows rb*32..+31; both columns
    // valid except the diagonal tile rb==W2 (col W1 masked, warp-uniform).
    // sup(i,j) == fmaf(iw, ih, -(c_i+c_j)) > 0  (algebraic iou > TH)
    {
        const int w    = tid >> 5;
        const int lane = tid & 31;
#pragma unroll 1
        for (int tt = 0; tt < 9; ++tt) {
            const int t  = w + tt * 8;
            const int p  = TP[t];
            const int rb = TRB[t];
            const int W1 = 2 * p;
            const int W2 = W1 + 1;
            const int j1 = (W1 << 5) + lane;
            const int j2 = (W2 << 5) + lane;
            const float4 b1 = bx4[j1];
            const float  c1 = s_c[j1];
            const float4 b2 = bx4[j2];
            const float  c2 = s_c[j2];
            const bool do1 = (rb <= W1);               // warp-uniform
            const int nw = 16 - rb;
            unsigned* dst1 = mat + tri_base(rb) + (W1 - rb);
#pragma unroll 4
            for (int rr = 0; rr < 32; ++rr) {
                const int r = (rb << 5) + rr;
                const float4 bi = bx4[r];               // broadcast LDS.128
                const float  ci = s_c[r];
                // column W2 (always valid)
                float xx1 = fmaxf(bi.x, b2.x);
                float yy1 = fmaxf(bi.y, b2.y);
                float xx2 = fminf(bi.z, b2.z);
                float yy2 = fminf(bi.w, b2.w);
                float iw = fmaxf(xx2 - xx1, 0.0f);
                float ih = fmaxf(yy2 - yy1, 0.0f);
                bool sup2 = fmaf(iw, ih, -(ci + c2)) > 0.0f;
                unsigned bits2 = __ballot_sync(0xFFFFFFFFu, sup2);
                // column W1
                float ax1 = fmaxf(bi.x, b1.x);
                float ay1 = fmaxf(bi.y, b1.y);
                float ax2 = fminf(bi.z, b1.z);
                float ay2 = fminf(bi.w, b1.w);
                float aw = fmaxf(ax2 - ax1, 0.0f);
                float ah = fmaxf(ay2 - ay1, 0.0f);
                bool sup1 = fmaf(aw, ah, -(ci + c1)) > 0.0f;
                unsigned bits1 = __ballot_sync(0xFFFFFFFFu, sup1);
                if (lane == 0) {
                    dst1[rr * nw + 1] = bits2;
                    if (do1) dst1[rr * nw] = bits1;
                }
            }
        }
    }
    __syncthreads();

    // ======== NMS walk on thread 0 (alive in regs), overlapped with
    //          output zero-fill by warps 1..7 ========
    if (tid == 0) {
        unsigned alive[16];
#pragma unroll
        for (int ww = 0; ww < 16; ++ww) {
            int n = K - ww * 32;
            alive[ww] = (n >= 32) ? 0xFFFFFFFFu : (n > 0 ? ((1u << n) - 1u) : 0u);
        }
        int cnt = 0;
#pragma unroll
        for (int W = 0; W < 16; ++W) {
            const int nw = 16 - W;
            const unsigned* blk = mat + tri_base(W);
            unsigned cur = alive[W];
            while (cur) {
                int bit = __ffs(cur) - 1;
                pord[cnt++] = (W << 5) + bit;
                const unsigned* mrow = blk + bit * nw;
                cur &= ~mrow[0];                 // self bit clears (iou=1 > TH)
#pragma unroll
                for (int ww = W + 1; ww < 16; ++ww)
                    alive[ww] &= ~mrow[ww - W];
            }
        }
        misc[7] = (unsigned)cnt;
    } else if (tid >= 32) {
        for (int e = tid - 32; e < TOPK * 5; e += NT - 32) outp[e] = 0.0f;
    }
    __syncthreads();

    // ======== writeout (live rows only; rest already zero) ========
    const int cnt = (int)misc[7];
    for (int t = tid; t < cnt; t += NT) {
        int p = pord[t];
        float4 bb = bx4[p];
        outp[t * 5 + 0] = sel_s[p];
        outp[t * 5 + 1] = bb.x;
        outp[t * 5 + 2] = bb.y;
        outp[t * 5 + 3] = bb.z;
        outp[t * 5 + 4] = bb.w;
    }
}

extern "C" void kernel_launch(void* const* d_in, const int* in_sizes, int n_in,
                              void* d_out, int out_size) {
    const float* arm_loc  = (const float*)d_in[0];
    const float* arm_conf = (const float*)d_in[1];
    const float* odm_loc  = (const float*)d_in[2];
    const float* odm_conf = (const float*)d_in[3];
    const float* priors   = (const float*)d_in[4];
    float* out = (float*)d_out;

    cudaFuncSetAttribute(task_kernel, cudaFuncAttributeMaxDynamicSharedMemorySize,
                         SMEM_TOTAL);

    int total = BATCH * PNUM;
    prep_kernel<<<(total + 255) / 256, 256>>>(arm_loc, arm_conf, odm_loc, odm_conf,
                                              priors);
    task_kernel<<<BATCH * NCLS, NT, SMEM_TOTAL>>>(out);
}

// round 12
// speedup vs baseline: 1.9175x; 1.0134x over previous
#include <cuda_runtime.h>

#define PNUM 16320
#define BATCH 32
#define NCLS 21
#define TOPK 500
#define CONF_THV 0.01f
#define NMS_THV 0.45f
#define OBJ_THV 0.01f
#define NT 256
// TH/(1+TH) for the transformed suppression test
#define NMS_COEF 0.310344827586206896f
#define NQ4 4080   // PNUM/4 float4 loads

// ---- device scratch (no allocations allowed) ----
__device__ float4 g_boxes[BATCH * PNUM];                 // decoded boxes (x1,y1,x2,y2)
__device__ float  g_scores[BATCH * (NCLS - 1) * PNUM];   // arm-masked scores, [B][20][P]

// ---- shared memory layout (bytes) ----
#define OFF_MISC   0        // 64 (16 u32)
#define OFF_SEL    64       // 512*8 = 4096 (u64 keys: score||~idx)
#define OFF_BOX    4160     // 512*16 = 8192 (16B aligned)
#define OFF_AREA   12352    // 2048  (holds c_i = NMS_COEF * area_i)
#define OFF_PORD   14400    // 2048
#define OFF_MAT    16448    // triangle-packed 4352 words = 17408
#define SMEM_TOTAL 33856    // single wave
// overlays inside MAT (dead until matrix phase)
#define OFF_HIST   16448    // 2048*4 = 8192
#define OFF_PART   24640    // 256*4
#define OFF_WSUM   25664    // 8*4
#define OFF_EQ     25696    // 512*4

// misc: 1=ncomp 2=THR 3=ntie 4=rem/take 5=done 6=K 7=cnt 8=prefix 9=neq 13=tieTake

// triangle packing: rows grouped by block rb=r>>5; row r stores words rb..15
__host__ __device__ __forceinline__ int tri_base(int rb) {
    return 512 * rb - 16 * rb * (rb - 1);
}

// 72 equal 32x32 tiles (p=column pair, rb=row block; rb <= 2p+1), 9 per warp
__device__ __constant__ unsigned char TP[72] = {
    0,0, 1,1,1,1, 2,2,2,2,2,2, 3,3,3,3,3,3,3,3,
    4,4,4,4,4,4,4,4,4,4, 5,5,5,5,5,5,5,5,5,5,5,5,
    6,6,6,6,6,6,6,6,6,6,6,6,6,6, 7,7,7,7,7,7,7,7,7,7,7,7,7,7,7,7};
__device__ __constant__ unsigned char TRB[72] = {
    0,1, 0,1,2,3, 0,1,2,3,4,5, 0,1,2,3,4,5,6,7,
    0,1,2,3,4,5,6,7,8,9, 0,1,2,3,4,5,6,7,8,9,10,11,
    0,1,2,3,4,5,6,7,8,9,10,11,12,13, 0,1,2,3,4,5,6,7,8,9,10,11,12,13,14,15};

// =====================================================================
// Kernel 1: cascaded decode + arm-masked score transpose
// =====================================================================
__global__ void prep_kernel(const float* __restrict__ arm_loc,
                            const float* __restrict__ arm_conf,
                            const float* __restrict__ odm_loc,
                            const float* __restrict__ odm_conf,
                            const float* __restrict__ priors) {
    int idx = blockIdx.x * blockDim.x + threadIdx.x;
    if (idx >= BATCH * PNUM) return;
    int b = idx / PNUM;
    int p = idx % PNUM;

    float pcx = priors[p * 4 + 0];
    float pcy = priors[p * 4 + 1];
    float pw  = priors[p * 4 + 2];
    float ph  = priors[p * 4 + 3];

    const float* al = arm_loc + (size_t)idx * 4;
    const float* ol = odm_loc + (size_t)idx * 4;

    float cx = pcx + al[0] * 0.1f * pw;
    float cy = pcy + al[1] * 0.1f * ph;
    float w  = pw * expf(al[2] * 0.2f);
    float h  = ph * expf(al[3] * 0.2f);
    float mnx = cx - w * 0.5f;
    float mny = cy - h * 0.5f;
    float mxx = mnx + w;
    float mxy = mny + h;
    float dcx = (mxx + mnx) * 0.5f;
    float dcy = (mxy + mny) * 0.5f;
    float dw  = mxx - mnx;
    float dh  = mxy - mny;

    float cx2 = dcx + ol[0] * 0.1f * dw;
    float cy2 = dcy + ol[1] * 0.1f * dh;
    float w2  = dw * expf(ol[2] * 0.2f);
    float h2  = dh * expf(ol[3] * 0.2f);
    float x1 = cx2 - w2 * 0.5f;
    float y1 = cy2 - h2 * 0.5f;
    float x2 = x1 + w2;
    float y2 = y1 + h2;
    g_boxes[idx] = make_float4(x1, y1, x2, y2);

    bool armpass = arm_conf[(size_t)idx * 2 + 1] > OBJ_THV;
    const float* oc = odm_conf + (size_t)idx * NCLS;
#pragma unroll
    for (int c = 1; c < NCLS; ++c) {
        float v = armpass ? oc[c] : 0.0f;
        g_scores[((size_t)(b * (NCLS - 1) + (c - 1))) * PNUM + p] = v;
    }
}

// =====================================================================
// Kernel 2: per (image,class), 256 threads. 32-bit 11/11/10-digit radix
// select, u64-key bitonic sort, adjacent-pair LUT-balanced suppression
// matrix, speculative 2-pivot register-resident NMS walk.
// =====================================================================
__global__ void __launch_bounds__(NT) task_kernel(float* __restrict__ out) {
    extern __shared__ __align__(16) char smraw[];
    unsigned*           misc = (unsigned*)(smraw + OFF_MISC);
    unsigned long long* sel  = (unsigned long long*)(smraw + OFF_SEL);
    float4*             bx4  = (float4*)(smraw + OFF_BOX);
    float*              s_c  = (float*)(smraw + OFF_AREA);
    int*                pord = (int*)(smraw + OFF_PORD);
    unsigned*           mat  = (unsigned*)(smraw + OFF_MAT);
    unsigned*           hist = (unsigned*)(smraw + OFF_HIST);
    unsigned*           part = (unsigned*)(smraw + OFF_PART);
    unsigned*           wsum = (unsigned*)(smraw + OFF_WSUM);
    unsigned*           eq   = (unsigned*)(smraw + OFF_EQ);

    const int tid = threadIdx.x;
    const int b   = blockIdx.x / NCLS;
    const int cl  = blockIdx.x % NCLS;
    float* outp = out + (size_t)(b * NCLS + cl) * (TOPK * 5);

    if (cl == 0) {  // background class: all zeros
        for (int e = tid; e < TOPK * 5; e += NT) outp[e] = 0.0f;
        return;
    }

    const float* __restrict__ sp =
        g_scores + (size_t)(b * (NCLS - 1) + (cl - 1)) * PNUM;
    const float4* __restrict__ sp4 = (const float4*)sp;

    // ======== PASS A: 2048-bin histogram on kb>>21 (match-aggregated) ========
    for (int h = tid; h < 2048; h += NT) hist[h] = 0u;
    if (tid < 16) misc[tid] = 0u;
    __syncthreads();

#pragma unroll 1
    for (int it = 0; it < 16; ++it) {          // uniform trip count
        int j4 = it * NT + tid;
        float4 sv = make_float4(0.f, 0.f, 0.f, 0.f);
        bool inb = j4 < NQ4;
        if (inb) sv = sp4[j4];
#pragma unroll
        for (int e = 0; e < 4; ++e) {
            float s = (e == 0) ? sv.x : (e == 1) ? sv.y : (e == 2) ? sv.z : sv.w;
            int bin = (inb && s > CONF_THV) ? (int)(__float_as_uint(s) >> 21) : -1;
            unsigned grp = __match_any_sync(0xFFFFFFFFu, bin);
            if (((unsigned)tid & 31u) == (unsigned)(__ffs(grp) - 1) && bin >= 0)
                atomicAdd(&hist[bin], (unsigned)__popc(grp));
        }
    }
    __syncthreads();
    {   // reduce 2048 bins: 8/thread -> part[256] -> wsum[8]
        unsigned v = 0;
#pragma unroll
        for (int q = 0; q < 8; ++q) v += hist[tid * 8 + q];
        part[tid] = v;
#pragma unroll
        for (int o = 16; o; o >>= 1) v += __shfl_down_sync(0xFFFFFFFFu, v, o);
        if ((tid & 31) == 0) wsum[tid >> 5] = v;
    }
    __syncthreads();
    if (tid == 0) {
        unsigned total = 0;
        for (int l = 0; l < 8; ++l) total += wsum[l];
        unsigned K = total < TOPK ? total : TOPK;
        misc[6] = K;
        if (K > 0) {
            unsigned rem = K, cum = 0;
            int l = 7;
            for (;; --l) { unsigned v = wsum[l]; if (cum + v >= rem) break; cum += v; }
            int p = l * 32 + 31;
            for (;; --p) { unsigned v = part[p]; if (cum + v >= rem) break; cum += v; }
            int bb = p * 8 + 7;
            for (;; --bb) { unsigned v = hist[bb]; if (cum + v >= rem) break; cum += v; }
            unsigned take = rem - cum;
            misc[8] = (unsigned)bb;
            misc[4] = take;
            if (take == hist[bb]) {       // whole 11-bit bin selected
                misc[2] = (unsigned)bb << 21;
                misc[3] = 0u;
                misc[5] = 1u;
            }
        }
    }
    __syncthreads();

    const int K = (int)misc[6];
    if (K == 0) {
        for (int e = tid; e < TOPK * 5; e += NT) outp[e] = 0.0f;
        return;
    }

    // ======== PASS B: bits 10..20 within bin bselA (plain atomics) ========
    if (!misc[5]) {
        const unsigned bselA = misc[8];
        for (int h = tid; h < 2048; h += NT) hist[h] = 0u;
        __syncthreads();
        for (int j4 = tid; j4 < NQ4; j4 += NT) {   // no collectives: divergence OK
            float4 sv = sp4[j4];
#pragma unroll
            for (int e = 0; e < 4; ++e) {
                float s = (e == 0) ? sv.x : (e == 1) ? sv.y : (e == 2) ? sv.z : sv.w;
                unsigned kb = __float_as_uint(s);
                if (s > CONF_THV && (kb >> 21) == bselA)
                    atomicAdd(&hist[(kb >> 10) & 0x7FFu], 1u);
            }
        }
        __syncthreads();
        {
            unsigned v = 0;
#pragma unroll
            for (int q = 0; q < 8; ++q) v += hist[tid * 8 + q];
            part[tid] = v;
#pragma unroll
            for (int o = 16; o; o >>= 1) v += __shfl_down_sync(0xFFFFFFFFu, v, o);
            if ((tid & 31) == 0) wsum[tid >> 5] = v;
        }
        __syncthreads();
        if (tid == 0) {
            unsigned rem = misc[4], cum = 0;
            int l = 7;
            for (;; --l) { unsigned v = wsum[l]; if (cum + v >= rem) break; cum += v; }
            int p = l * 32 + 31;
            for (;; --p) { unsigned v = part[p]; if (cum + v >= rem) break; cum += v; }
            int bb = p * 8 + 7;
            for (;; --bb) { unsigned v = hist[bb]; if (cum + v >= rem) break; cum += v; }
            unsigned take = rem - cum;
            unsigned pfx2 = (bselA << 11) | (unsigned)bb;
            misc[8] = pfx2;
            misc[4] = take;
            if (take == hist[bb]) {
                misc[2] = pfx2 << 10;
                misc[3] = 0u;
                misc[5] = 1u;
            }
        }
        __syncthreads();
    }

    // ======== PASS C (rare): bits 0..9 within 22-bit prefix ========
    if (!misc[5]) {
        const unsigned pfx2 = misc[8];
        for (int h = tid; h < 1024; h += NT) hist[h] = 0u;
        __syncthreads();
        for (int j4 = tid; j4 < NQ4; j4 += NT) {
            float4 sv = sp4[j4];
#pragma unroll
            for (int e = 0; e < 4; ++e) {
                float s = (e == 0) ? sv.x : (e == 1) ? sv.y : (e == 2) ? sv.z : sv.w;
                unsigned kb = __float_as_uint(s);
                if (s > CONF_THV && (kb >> 10) == pfx2)
                    atomicAdd(&hist[kb & 0x3FFu], 1u);
            }
        }
        __syncthreads();
        {
            unsigned v = 0;
#pragma unroll
            for (int q = 0; q < 4; ++q) v += hist[tid * 4 + q];
            part[tid] = v;
#pragma unroll
            for (int o = 16; o; o >>= 1) v += __shfl_down_sync(0xFFFFFFFFu, v, o);
            if ((tid & 31) == 0) wsum[tid >> 5] = v;
        }
        __syncthreads();
        if (tid == 0) {
            unsigned rem = misc[4], cum = 0;
            int l = 7;
            for (;; --l) { unsigned v = wsum[l]; if (cum + v >= rem) break; cum += v; }
            int p = l * 32 + 31;
            for (;; --p) { unsigned v = part[p]; if (cum + v >= rem) break; cum += v; }
            int bb = p * 4 + 3;
            for (;; --bb) { unsigned v = hist[bb]; if (cum + v >= rem) break; cum += v; }
            unsigned take = rem - cum;
            misc[2] = (pfx2 << 10) | (unsigned)bb;     // exact 32-bit score
            if (take == hist[bb]) {
                misc[3] = 0u;
            } else {
                misc[3] = 1u;                          // tie among identical scores
                misc[13] = take;
            }
        }
        __syncthreads();
    }

    // ======== final compaction scan (writes packed u64 keys) ========
    const unsigned THR  = misc[2];
    const unsigned ntie = misc[3];
#pragma unroll 1
    for (int it = 0; it < 16; ++it) {                  // uniform trips (ballot)
        int j4 = it * NT + tid;
        float4 sv = make_float4(0.f, 0.f, 0.f, 0.f);
        bool inb = j4 < NQ4;
        if (inb) sv = sp4[j4];
#pragma unroll
        for (int e = 0; e < 4; ++e) {
            float s = (e == 0) ? sv.x : (e == 1) ? sv.y : (e == 2) ? sv.z : sv.w;
            unsigned kb = __float_as_uint(s);
            bool cand = inb && (s > CONF_THV);
            bool selb = cand && (ntie ? (kb > THR) : (kb >= THR));
            unsigned m = __ballot_sync(0xFFFFFFFFu, selb);
            unsigned base = 0;
            if ((tid & 31) == 0 && m) base = atomicAdd(&misc[1], (unsigned)__popc(m));
            base = __shfl_sync(0xFFFFFFFFu, base, 0);
            if (selb) {
                unsigned pos = base + __popc(m & ((1u << (tid & 31)) - 1u));
                sel[pos] = ((unsigned long long)kb << 32) |
                           (unsigned long long)(0xFFFFFFFFu - (unsigned)(j4 * 4 + e));
            }
            if (ntie && cand && kb == THR) {
                unsigned p = atomicAdd(&misc[9], 1u);
                if (p < 512) eq[p] = (unsigned)(j4 * 4 + e);
            }
        }
    }
    __syncthreads();
    if (ntie && tid == 0) {    // take smallest indices among exact-score ties
        int neq = (int)misc[9]; if (neq > 512) neq = 512;
        int take = (int)misc[13]; if (take > neq) take = neq;
        int base = (int)misc[1];
        for (int t = 0; t < take; ++t) {
            unsigned best = 0xFFFFFFFFu; int bi = 0;
            for (int q = 0; q < neq; ++q)
                if (eq[q] < best) { best = eq[q]; bi = q; }
            eq[bi] = 0xFFFFFFFFu;
            sel[base + t] = ((unsigned long long)THR << 32) |
                            (unsigned long long)(0xFFFFFFFFu - best);
        }
        misc[1] = (unsigned)(base + take);
    }
    __syncthreads();
    for (int i = tid; i < 512; i += NT)
        if (i >= K) sel[i] = (unsigned long long)(0xBFFFFFFFu - i);  // hi32=0: sorts last
    __syncthreads();

    // ======== bitonic sort 512 u64 keys (2 elems/thread), descending ========
    for (unsigned k = 2; k <= 512; k <<= 1) {
        for (unsigned jj = k >> 1; jj > 0; jj >>= 1) {
#pragma unroll
            for (int half = 0; half < 512; half += NT) {
                unsigned i = (unsigned)(half + tid);
                unsigned ixj = i ^ jj;
                if (ixj > i) {
                    unsigned long long a = sel[i], x = sel[ixj];
                    bool g = x > a;                 // == (score desc, idx asc)
                    bool asc = ((i & k) == 0);
                    if (asc ? g : !g) { sel[i] = x; sel[ixj] = a; }
                }
            }
            __syncthreads();
        }
    }

    // ======== gather boxes + precompute c_i = NMS_COEF * area_i ========
    for (int i = tid; i < 512; i += NT) {
        float4 bb = make_float4(0.f, 0.f, 0.f, 0.f);
        float a = 0.f;
        if (i < K) {
            unsigned idx = 0xFFFFFFFFu - (unsigned)sel[i];
            bb = g_boxes[(size_t)b * PNUM + idx];
            a = (bb.z - bb.x) * (bb.w - bb.y);
        }
        bx4[i] = bb;
        s_c[i] = NMS_COEF * a;
    }
    __syncthreads();

    // ======== suppression matrix over 72 balanced adjacent-pair tiles ========
    // sup(i,j) == fmaf(iw, ih, -(c_i+c_j)) > 0 ; iw clamped, ih clamp dropped
    // (iw >= 0 and threshold > 0 make a negative ih-product always fail).
    {
        const int w    = tid >> 5;
        const int lane = tid & 31;
#pragma unroll 1
        for (int tt = 0; tt < 9; ++tt) {
            const int t  = w + tt * 8;
            const int p  = TP[t];
            const int rb = TRB[t];
            const int W1 = 2 * p;
            const int W2 = W1 + 1;
            const int j1 = (W1 << 5) + lane;
            const int j2 = (W2 << 5) + lane;
            const float4 b1 = bx4[j1];
            const float  c1 = s_c[j1];
            const float4 b2 = bx4[j2];
            const float  c2 = s_c[j2];
            const bool do1 = (rb <= W1);               // warp-uniform
            const int nw = 16 - rb;
            unsigned* dst1 = mat + tri_base(rb) + (W1 - rb);
#pragma unroll 4
            for (int rr = 0; rr < 32; ++rr) {
                const int r = (rb << 5) + rr;
                const float4 bi = bx4[r];               // broadcast LDS.128
                const float  ci = s_c[r];
                // column W2 (always valid)
                float xx1 = fmaxf(bi.x, b2.x);
                float yy1 = fmaxf(bi.y, b2.y);
                float xx2 = fminf(bi.z, b2.z);
                float yy2 = fminf(bi.w, b2.w);
                float iw = fmaxf(xx2 - xx1, 0.0f);
                float ih = yy2 - yy1;                   // unclamped: safe
                bool sup2 = fmaf(iw, ih, -(ci + c2)) > 0.0f;
                unsigned bits2 = __ballot_sync(0xFFFFFFFFu, sup2);
                // column W1
                float ax1 = fmaxf(bi.x, b1.x);
                float ay1 = fmaxf(bi.y, b1.y);
                float ax2 = fminf(bi.z, b1.z);
                float ay2 = fminf(bi.w, b1.w);
                float aw = fmaxf(ax2 - ax1, 0.0f);
                float ah = ay2 - ay1;                   // unclamped: safe
                bool sup1 = fmaf(aw, ah, -(ci + c1)) > 0.0f;
                unsigned bits1 = __ballot_sync(0xFFFFFFFFu, sup1);
                if (lane == 0) {
                    dst1[rr * nw + 1] = bits2;
                    if (do1) dst1[rr * nw] = bits1;
                }
            }
        }
    }
    __syncthreads();

    // ======== speculative 2-pivot NMS walk (thread 0, alive in regs),
    //          overlapped with output zero-fill by warps 1..7 ========
    if (tid == 0) {
        unsigned alive[16];
#pragma unroll
        for (int ww = 0; ww < 16; ++ww) {
            int n = K - ww * 32;
            alive[ww] = (n >= 32) ? 0xFFFFFFFFu : (n > 0 ? ((1u << n) - 1u) : 0u);
        }
        int cnt = 0;
#pragma unroll
        for (int W = 0; W < 16; ++W) {
            const int nw = 16 - W;
            const unsigned* blk = mat + tri_base(W);
            unsigned cur = alive[W];
            while (cur) {
                int b1 = __ffs(cur) - 1;
                const unsigned* r1 = blk + b1 * nw;
                unsigned m1 = r1[0];                    // chain load
                // speculative next pivot (independent of m1)
                unsigned spec = cur & ~(1u << b1);
                int b2 = spec ? (__ffs(spec) - 1) : 32;
                const unsigned* r2 = blk + ((b2 < 32) ? b2 : b1) * nw;
                unsigned m2 = r2[0];                    // prefetch
                pord[cnt++] = (W << 5) + b1;
#pragma unroll
                for (int ww = W + 1; ww < 16; ++ww)
                    alive[ww] &= ~r1[ww - W];
                cur &= ~m1;                             // self bit clears too
                cur &= ~(1u << b1);
                if (b2 < 32 && ((cur >> b2) & 1u)) {    // speculation hit
                    pord[cnt++] = (W << 5) + b2;
#pragma unroll
                    for (int ww = W + 1; ww < 16; ++ww)
                        alive[ww] &= ~r2[ww - W];
                    cur &= ~m2;
                    cur &= ~(1u << b2);
                }
            }
        }
        misc[7] = (unsigned)cnt;
    } else if (tid >= 32) {
        for (int e = tid - 32; e < TOPK * 5; e += NT - 32) outp[e] = 0.0f;
    }
    __syncthreads();

    // ======== writeout (live rows only; rest already zero) ========
    const int cnt = (int)misc[7];
    for (int t = tid; t < cnt; t += NT) {
        int p = pord[t];
        float4 bb = bx4[p];
        outp[t * 5 + 0] = __uint_as_float((unsigned)(sel[p] >> 32));
        outp[t * 5 + 1] = bb.x;
        outp[t * 5 + 2] = bb.y;
        outp[t * 5 + 3] = bb.z;
        outp[t * 5 + 4] = bb.w;
    }
}

extern "C" void kernel_launch(void* const* d_in, const int* in_sizes, int n_in,
                              void* d_out, int out_size) {
    const float* arm_loc  = (const float*)d_in[0];
    const float* arm_conf = (const float*)d_in[1];
    const float* odm_loc  = (const float*)d_in[2];
    const float* odm_conf = (const float*)d_in[3];
    const float* priors   = (const float*)d_in[4];
    float* out = (float*)d_out;

    cudaFuncSetAttribute(task_kernel, cudaFuncAttributeMaxDynamicSharedMemorySize,
                         SMEM_TOTAL);

    int total = BATCH * PNUM;
    prep_kernel<<<(total + 255) / 256, 256>>>(arm_loc, arm_conf, odm_loc, odm_conf,
                                              priors);
    task_kernel<<<BATCH * NCLS, NT, SMEM_TOTAL>>>(out);
}